// round 1
// baseline (speedup 1.0000x reference)
#include <cuda_runtime.h>
#include <cstdint>

#define N_NODES 50000
#define N_EDGES 800000
#define D 128
#define BN_EPS 1e-3f

#define ET 64          // edges per tile
#define NT 64          // nodes per tile
#define PAD 132        // padded smem row length in floats (k-dim), keeps 16B alignment, reduces conflicts

// Scratch (static device allocations are allowed; runtime allocs are not)
__device__ float g_hidden[N_NODES * D];   // node_hidden = nf @ W_node + b_node
__device__ float g_counts[N_NODES];       // per-node edge counts (float, matches reference)

// ---------------------------------------------------------------------------
// helpers
// ---------------------------------------------------------------------------
__device__ __forceinline__ void red_add_v4(float* addr, float a, float b, float c, float d) {
    asm volatile("red.global.add.v4.f32 [%0], {%1, %2, %3, %4};"
                 :: "l"(addr), "f"(a), "f"(b), "f"(c), "f"(d) : "memory");
}

__device__ __forceinline__ float sigmoidf_fast(float x) {
    return 1.0f / (1.0f + __expf(-x));
}

// ---------------------------------------------------------------------------
// K0: zero the accumulator (d_out doubles as segment-sum buffer) and counts
// ---------------------------------------------------------------------------
__global__ void zero_kernel(float* __restrict__ out) {
    int idx = blockIdx.x * blockDim.x + threadIdx.x;
    int stride = gridDim.x * blockDim.x;
    const int nv4 = N_NODES * D / 4;
    float4 z = make_float4(0.f, 0.f, 0.f, 0.f);
    for (int i = idx; i < nv4; i += stride)
        reinterpret_cast<float4*>(out)[i] = z;
    for (int i = idx; i < N_NODES; i += stride)
        g_counts[i] = 0.f;
}

// ---------------------------------------------------------------------------
// K1: node_hidden = node_features @ W_node + b_node   (persistent tiled GEMM)
// 256 threads: tx = t%32 -> 4 cols, ty = t/32 -> 8 rows. Tile = 64 rows x 128.
// ---------------------------------------------------------------------------
__global__ __launch_bounds__(256, 2)
void node_gemm_kernel(const float* __restrict__ nf,
                      const float* __restrict__ W,
                      const float* __restrict__ b) {
    extern __shared__ float sm[];
    float* sW = sm;              // 128 * PAD
    float* sX = sm + 128 * PAD;  // NT  * PAD

    const int t  = threadIdx.x;
    const int tx = t & 31;
    const int ty = t >> 5;

    // Load W (row-major [k][j]) into smem once per CTA
    for (int i = t; i < 128 * 32; i += 256) {
        int r = i >> 5, q = i & 31;
        *reinterpret_cast<float4*>(&sW[r * PAD + q * 4]) =
            *reinterpret_cast<const float4*>(&W[r * D + q * 4]);
    }
    float4 bb = *reinterpret_cast<const float4*>(&b[tx * 4]);

    const int ntiles = (N_NODES + NT - 1) / NT;
    for (int tile = blockIdx.x; tile < ntiles; tile += gridDim.x) {
        __syncthreads();  // guard sX reuse across iterations
        const int row0 = tile * NT;
        for (int i = t; i < NT * 32; i += 256) {
            int r = i >> 5, q = i & 31;
            int row = row0 + r;
            float4 v = make_float4(0.f, 0.f, 0.f, 0.f);
            if (row < N_NODES)
                v = *reinterpret_cast<const float4*>(&nf[row * D + q * 4]);
            *reinterpret_cast<float4*>(&sX[r * PAD + q * 4]) = v;
        }
        __syncthreads();

        float acc[8][4];
        #pragma unroll
        for (int i = 0; i < 8; i++)
            #pragma unroll
            for (int c = 0; c < 4; c++) acc[i][c] = 0.f;

        #pragma unroll 4
        for (int k4 = 0; k4 < 32; k4++) {
            float ev[8][4];
            #pragma unroll
            for (int i = 0; i < 8; i++) {
                float4 v = *reinterpret_cast<float4*>(&sX[(ty * 8 + i) * PAD + k4 * 4]);
                ev[i][0] = v.x; ev[i][1] = v.y; ev[i][2] = v.z; ev[i][3] = v.w;
            }
            #pragma unroll
            for (int kk = 0; kk < 4; kk++) {
                float4 w = *reinterpret_cast<float4*>(&sW[(k4 * 4 + kk) * PAD + tx * 4]);
                #pragma unroll
                for (int i = 0; i < 8; i++) {
                    float e = ev[i][kk];
                    acc[i][0] += e * w.x;
                    acc[i][1] += e * w.y;
                    acc[i][2] += e * w.z;
                    acc[i][3] += e * w.w;
                }
            }
        }

        #pragma unroll
        for (int i = 0; i < 8; i++) {
            int row = row0 + ty * 8 + i;
            if (row < N_NODES) {
                float4 o;
                o.x = acc[i][0] + bb.x;
                o.y = acc[i][1] + bb.y;
                o.z = acc[i][2] + bb.z;
                o.w = acc[i][3] + bb.w;
                *reinterpret_cast<float4*>(&g_hidden[row * D + tx * 4]) = o;
            }
        }
    }
}

// ---------------------------------------------------------------------------
// K2: per-edge gate/filt GEMMs fused with gather + message + scatter-add.
// Persistent: W_gate and W_filt resident in SMEM for the CTA lifetime.
// 256 threads: tx = t%32 -> 4 cols, ty = t/32 -> 8 edges. Tile = 64 edges.
// Each thread keeps BOTH gate and filt accumulators for its (edge, col) block,
// so messages are formed entirely in registers.
// ---------------------------------------------------------------------------
__global__ __launch_bounds__(256, 1)
void edge_kernel(const float* __restrict__ ef,
                 const float* __restrict__ Wg, const float* __restrict__ bg,
                 const float* __restrict__ Wf, const float* __restrict__ bf,
                 const int*   __restrict__ eidx,
                 float* __restrict__ out) {
    extern __shared__ float sm[];
    float* sWg = sm;                  // 128 * PAD
    float* sWf = sm + 128 * PAD;      // 128 * PAD
    float* sE  = sm + 2 * 128 * PAD;  // ET * PAD
    int*   sSrc = reinterpret_cast<int*>(sE + ET * PAD);
    int*   sDst = sSrc + ET;

    const int t  = threadIdx.x;
    const int tx = t & 31;
    const int ty = t >> 5;

    for (int i = t; i < 128 * 32; i += 256) {
        int r = i >> 5, q = i & 31;
        *reinterpret_cast<float4*>(&sWg[r * PAD + q * 4]) =
            *reinterpret_cast<const float4*>(&Wg[r * D + q * 4]);
        *reinterpret_cast<float4*>(&sWf[r * PAD + q * 4]) =
            *reinterpret_cast<const float4*>(&Wf[r * D + q * 4]);
    }
    float4 bgv = *reinterpret_cast<const float4*>(&bg[tx * 4]);
    float4 bfv = *reinterpret_cast<const float4*>(&bf[tx * 4]);

    const int ntiles = N_EDGES / ET;  // 12500, exact
    for (int tile = blockIdx.x; tile < ntiles; tile += gridDim.x) {
        __syncthreads();  // guard sE/sSrc/sDst reuse
        const int e0 = tile * ET;
        if (t < ET) {
            int2 p = *reinterpret_cast<const int2*>(&eidx[(e0 + t) * 2]);
            sSrc[t] = p.x;  // segment (destination of aggregation)
            sDst[t] = p.y;  // neighbor (gather index)
        }
        for (int i = t; i < ET * 32; i += 256) {
            int r = i >> 5, q = i & 31;
            *reinterpret_cast<float4*>(&sE[r * PAD + q * 4]) =
                *reinterpret_cast<const float4*>(&ef[(e0 + r) * D + q * 4]);
        }
        __syncthreads();

        float ag[8][4], af[8][4];
        #pragma unroll
        for (int i = 0; i < 8; i++)
            #pragma unroll
            for (int c = 0; c < 4; c++) { ag[i][c] = 0.f; af[i][c] = 0.f; }

        #pragma unroll 2
        for (int k4 = 0; k4 < 32; k4++) {
            float ev[8][4];
            #pragma unroll
            for (int i = 0; i < 8; i++) {
                float4 v = *reinterpret_cast<float4*>(&sE[(ty * 8 + i) * PAD + k4 * 4]);
                ev[i][0] = v.x; ev[i][1] = v.y; ev[i][2] = v.z; ev[i][3] = v.w;
            }
            #pragma unroll
            for (int kk = 0; kk < 4; kk++) {
                float4 wg = *reinterpret_cast<float4*>(&sWg[(k4 * 4 + kk) * PAD + tx * 4]);
                float4 wf = *reinterpret_cast<float4*>(&sWf[(k4 * 4 + kk) * PAD + tx * 4]);
                #pragma unroll
                for (int i = 0; i < 8; i++) {
                    float e = ev[i][kk];
                    ag[i][0] += e * wg.x; ag[i][1] += e * wg.y;
                    ag[i][2] += e * wg.z; ag[i][3] += e * wg.w;
                    af[i][0] += e * wf.x; af[i][1] += e * wf.y;
                    af[i][2] += e * wf.z; af[i][3] += e * wf.w;
                }
            }
        }

        // counts: one lane per edge
        if (t < ET) atomicAdd(&g_counts[sSrc[t]], 1.0f);

        // epilogue: gate = sigmoid(.), msg = gate * filt * hidden[dst], scatter into out[src]
        #pragma unroll
        for (int i = 0; i < 8; i++) {
            const int e   = ty * 8 + i;
            const int dst = sDst[e];
            const int src = sSrc[e];
            float4 nb = *reinterpret_cast<const float4*>(&g_hidden[dst * D + tx * 4]);
            float g0 = sigmoidf_fast(ag[i][0] + bgv.x);
            float g1 = sigmoidf_fast(ag[i][1] + bgv.y);
            float g2 = sigmoidf_fast(ag[i][2] + bgv.z);
            float g3 = sigmoidf_fast(ag[i][3] + bgv.w);
            float m0 = g0 * (af[i][0] + bfv.x) * nb.x;
            float m1 = g1 * (af[i][1] + bfv.y) * nb.y;
            float m2 = g2 * (af[i][2] + bfv.z) * nb.z;
            float m3 = g3 * (af[i][3] + bfv.w) * nb.w;
            red_add_v4(&out[src * D + tx * 4], m0, m1, m2, m3);
        }
    }
}

// ---------------------------------------------------------------------------
// K3: out = relu(bn(node_hidden + sums / max(counts,1)))
// out currently holds the segment sums; counts==0 implies sums==0 so the
// jnp.where branch is equivalent to dividing by max(counts,1).
// ---------------------------------------------------------------------------
__global__ void finalize_kernel(const float* __restrict__ gamma,
                                const float* __restrict__ beta,
                                const float* __restrict__ mean,
                                const float* __restrict__ var,
                                float* __restrict__ out) {
    int idx = blockIdx.x * blockDim.x + threadIdx.x;  // one float4 per thread
    const int total = N_NODES * 32;
    if (idx >= total) return;
    int node = idx >> 5;
    int q    = idx & 31;
    float inv = 1.f / fmaxf(g_counts[node], 1.f);

    float4 s  = reinterpret_cast<float4*>(out)[idx];
    float4 h  = *reinterpret_cast<const float4*>(&g_hidden[node * D + q * 4]);
    float4 mu = *reinterpret_cast<const float4*>(&mean[q * 4]);
    float4 vr = *reinterpret_cast<const float4*>(&var[q * 4]);
    float4 ga = *reinterpret_cast<const float4*>(&gamma[q * 4]);
    float4 be = *reinterpret_cast<const float4*>(&beta[q * 4]);

    float4 o;
    o.x = fmaxf((h.x + s.x * inv - mu.x) * rsqrtf(vr.x + BN_EPS) * ga.x + be.x, 0.f);
    o.y = fmaxf((h.y + s.y * inv - mu.y) * rsqrtf(vr.y + BN_EPS) * ga.y + be.y, 0.f);
    o.z = fmaxf((h.z + s.z * inv - mu.z) * rsqrtf(vr.z + BN_EPS) * ga.z + be.z, 0.f);
    o.w = fmaxf((h.w + s.w * inv - mu.w) * rsqrtf(vr.w + BN_EPS) * ga.w + be.w, 0.f);
    reinterpret_cast<float4*>(out)[idx] = o;
}

// ---------------------------------------------------------------------------
// launch
// ---------------------------------------------------------------------------
extern "C" void kernel_launch(void* const* d_in, const int* in_sizes, int n_in,
                              void* d_out, int out_size) {
    const float* nf    = (const float*)d_in[0];
    const float* ef    = (const float*)d_in[1];
    const float* Wn    = (const float*)d_in[2];
    const float* bn_   = (const float*)d_in[3];
    const float* Wg    = (const float*)d_in[4];
    const float* bg    = (const float*)d_in[5];
    const float* Wf    = (const float*)d_in[6];
    const float* bf    = (const float*)d_in[7];
    const float* gamma = (const float*)d_in[8];
    const float* beta  = (const float*)d_in[9];
    const float* mean  = (const float*)d_in[10];
    const float* var   = (const float*)d_in[11];
    const int*   eidx  = (const int*)d_in[12];
    float* out = (float*)d_out;

    const int node_smem = (128 * PAD + NT * PAD) * (int)sizeof(float);
    const int edge_smem = (2 * 128 * PAD + ET * PAD) * (int)sizeof(float) + 2 * ET * (int)sizeof(int);

    int dev = 0, nsm = 148;
    cudaGetDevice(&dev);
    cudaDeviceGetAttribute(&nsm, cudaDevAttrMultiProcessorCount, dev);
    cudaFuncSetAttribute(node_gemm_kernel, cudaFuncAttributeMaxDynamicSharedMemorySize, node_smem);
    cudaFuncSetAttribute(edge_kernel,      cudaFuncAttributeMaxDynamicSharedMemorySize, edge_smem);

    zero_kernel<<<512, 256>>>(out);
    node_gemm_kernel<<<2 * nsm, 256, node_smem>>>(nf, Wn, bn_);
    edge_kernel<<<nsm, 256, edge_smem>>>(ef, Wg, bg, Wf, bf, eidx, out);
    finalize_kernel<<<(N_NODES * 32 + 255) / 256, 256>>>(gamma, beta, mean, var, out);
}

// round 4
// speedup vs baseline: 1.6032x; 1.6032x over previous
#include <cuda_runtime.h>
#include <cuda_bf16.h>
#include <cstdint>

#define N_NODES 50000
#define N_EDGES 800000
#define D 128
#define BN_EPS 1e-3f

#define NT 64          // nodes per tile (node gemm)
#define PAD 132        // node gemm smem padding

#define PK 136         // bf16 elements per smem row (pitch), 272 B
#define AB 272         // bytes per smem row
#define WBUF 34816     // bytes per 128x136 bf16 buffer

// Scratch
__device__ float g_hidden[N_NODES * D];
__device__ float g_counts[N_NODES];

// ---------------------------------------------------------------------------
// helpers
// ---------------------------------------------------------------------------
__device__ __forceinline__ uint32_t smem_u32(const void* p) {
    uint32_t a;
    asm("{ .reg .u64 t; cvta.to.shared.u64 t, %1; cvt.u32.u64 %0, t; }" : "=r"(a) : "l"(p));
    return a;
}

__device__ __forceinline__ void red_add_v2(float* addr, float a, float b) {
    asm volatile("red.global.add.v2.f32 [%0], {%1, %2};"
                 :: "l"(addr), "f"(a), "f"(b) : "memory");
}

__device__ __forceinline__ void ldsm_x4(uint32_t* r, uint32_t addr) {
    asm volatile("ldmatrix.sync.aligned.m8n8.x4.shared.b16 {%0,%1,%2,%3}, [%4];"
                 : "=r"(r[0]), "=r"(r[1]), "=r"(r[2]), "=r"(r[3]) : "r"(addr));
}

__device__ __forceinline__ void mma_bf16(float* c, const uint32_t* a, const uint32_t* b) {
    asm volatile("mma.sync.aligned.m16n8k16.row.col.f32.bf16.bf16.f32 "
                 "{%0,%1,%2,%3}, {%4,%5,%6,%7}, {%8,%9}, {%0,%1,%2,%3};"
                 : "+f"(c[0]), "+f"(c[1]), "+f"(c[2]), "+f"(c[3])
                 : "r"(a[0]), "r"(a[1]), "r"(a[2]), "r"(a[3]), "r"(b[0]), "r"(b[1]));
}

__device__ __forceinline__ uint32_t pack_bf16(__nv_bfloat16 lo, __nv_bfloat16 hi) {
    return (uint32_t)__bfloat16_as_ushort(lo) | ((uint32_t)__bfloat16_as_ushort(hi) << 16);
}

// ---------------------------------------------------------------------------
// K0: zero accumulator + counts
// ---------------------------------------------------------------------------
__global__ void zero_kernel(float* __restrict__ out) {
    int idx = blockIdx.x * blockDim.x + threadIdx.x;
    int stride = gridDim.x * blockDim.x;
    const int nv4 = N_NODES * D / 4;
    float4 z = make_float4(0.f, 0.f, 0.f, 0.f);
    for (int i = idx; i < nv4; i += stride)
        reinterpret_cast<float4*>(out)[i] = z;
    for (int i = idx; i < N_NODES; i += stride)
        g_counts[i] = 0.f;
}

// ---------------------------------------------------------------------------
// K1: node_hidden = nf @ W_node + b_node  (fp32, exact)
// ---------------------------------------------------------------------------
__global__ __launch_bounds__(256, 2)
void node_gemm_kernel(const float* __restrict__ nf,
                      const float* __restrict__ W,
                      const float* __restrict__ b) {
    extern __shared__ float sm[];
    float* sW = sm;
    float* sX = sm + 128 * PAD;
    const int t = threadIdx.x, tx = t & 31, ty = t >> 5;

    for (int i = t; i < 128 * 32; i += 256) {
        int r = i >> 5, q = i & 31;
        *reinterpret_cast<float4*>(&sW[r * PAD + q * 4]) =
            *reinterpret_cast<const float4*>(&W[r * D + q * 4]);
    }
    float4 bb = *reinterpret_cast<const float4*>(&b[tx * 4]);

    const int ntiles = (N_NODES + NT - 1) / NT;
    for (int tile = blockIdx.x; tile < ntiles; tile += gridDim.x) {
        __syncthreads();
        const int row0 = tile * NT;
        for (int i = t; i < NT * 32; i += 256) {
            int r = i >> 5, q = i & 31;
            int row = row0 + r;
            float4 v = make_float4(0.f, 0.f, 0.f, 0.f);
            if (row < N_NODES)
                v = *reinterpret_cast<const float4*>(&nf[row * D + q * 4]);
            *reinterpret_cast<float4*>(&sX[r * PAD + q * 4]) = v;
        }
        __syncthreads();

        float acc[8][4];
        #pragma unroll
        for (int i = 0; i < 8; i++)
            #pragma unroll
            for (int c = 0; c < 4; c++) acc[i][c] = 0.f;

        #pragma unroll 4
        for (int k4 = 0; k4 < 32; k4++) {
            float ev[8][4];
            #pragma unroll
            for (int i = 0; i < 8; i++) {
                float4 v = *reinterpret_cast<float4*>(&sX[(ty * 8 + i) * PAD + k4 * 4]);
                ev[i][0] = v.x; ev[i][1] = v.y; ev[i][2] = v.z; ev[i][3] = v.w;
            }
            #pragma unroll
            for (int kk = 0; kk < 4; kk++) {
                float4 w = *reinterpret_cast<float4*>(&sW[(k4 * 4 + kk) * PAD + tx * 4]);
                #pragma unroll
                for (int i = 0; i < 8; i++) {
                    float e = ev[i][kk];
                    acc[i][0] += e * w.x; acc[i][1] += e * w.y;
                    acc[i][2] += e * w.z; acc[i][3] += e * w.w;
                }
            }
        }
        #pragma unroll
        for (int i = 0; i < 8; i++) {
            int row = row0 + ty * 8 + i;
            if (row < N_NODES) {
                float4 o;
                o.x = acc[i][0] + bb.x; o.y = acc[i][1] + bb.y;
                o.z = acc[i][2] + bb.z; o.w = acc[i][3] + bb.w;
                *reinterpret_cast<float4*>(&g_hidden[row * D + tx * 4]) = o;
            }
        }
    }
}

// ---------------------------------------------------------------------------
// K2: edge kernel — mma.sync bf16x3 split GEMMs (gate & filt) + fused epilogue
//
// Tile: M=128 edges x N=128 x K=128 per CTA iteration. Persistent CTAs.
// SMEM layout (bytes):
//   [0]     sSrc[128]  [512] sDst[128]  [1024] sBg[128]  [1536] sBf[128]
//   [2048]  A_hi [128][PK] bf16          (34816)
//   [36864] A_lo [128][PK] bf16          (34816)
//   [71680] W bufs x4: g_hi, g_lo, f_hi, f_lo — each W^T [n=128][k=PK] bf16
// total 210944.  1 CTA/SM, 256 threads.
//
// Warp grid 4(M) x 2(N): warp tile 32x64. Per warp: 2 m16 tiles x 8 n8 tiles.
// Split passes per k16 step, per matrix: Ahi*Bhi, Alo*Bhi, Ahi*Blo.
// Epilogue: each thread owns (row, col-pair) fragments -> gather hidden[dst],
// msg = sigmoid(g+bg)*(f+bf)*nb, red.global.add.v2 into out[src].
// ---------------------------------------------------------------------------
#define EK_SMEM 210944
#define OFF_A   2048
#define OFF_W   71680

__global__ __launch_bounds__(256, 1)
void edge_kernel(const float* __restrict__ ef,
                 const float* __restrict__ Wg, const float* __restrict__ bgp,
                 const float* __restrict__ Wf, const float* __restrict__ bfp,
                 const int*   __restrict__ eidx,
                 float* __restrict__ out) {
    extern __shared__ __align__(16) char smem[];
    int*   sSrc = reinterpret_cast<int*>(smem);
    int*   sDst = reinterpret_cast<int*>(smem + 512);
    float* sBg  = reinterpret_cast<float*>(smem + 1024);
    float* sBf  = reinterpret_cast<float*>(smem + 1536);
    char*  sA_hi = smem + OFF_A;
    char*  sA_lo = smem + OFF_A + WBUF;
    char*  sW    = smem + OFF_W;

    const int t = threadIdx.x, w = t >> 5, lane = t & 31;
    const int wm = w & 3, wn = w >> 2;

    if (t < 128) { sBg[t] = bgp[t]; sBf[t] = bfp[t]; }

    // Load + split + transpose W matrices into resident SMEM (one-time)
    for (int m = 0; m < 2; m++) {
        const float* W = m ? Wf : Wg;
        char* bh = sW + m * (2 * WBUF);
        char* bl = bh + WBUF;
        for (int idx = t; idx < 16384; idx += 256) {
            int k = idx >> 7, n = idx & 127;
            float wv = W[idx];
            __nv_bfloat16 h = __float2bfloat16(wv);
            __nv_bfloat16 l = __float2bfloat16(wv - __bfloat162float(h));
            *reinterpret_cast<__nv_bfloat16*>(bh + n * AB + k * 2) = h;
            *reinterpret_cast<__nv_bfloat16*>(bl + n * AB + k * 2) = l;
        }
    }
    __syncthreads();

    const uint32_t sbA_hi = smem_u32(sA_hi);
    const uint32_t sbA_lo = smem_u32(sA_lo);
    const uint32_t sbW    = smem_u32(sW);

    // ldmatrix lane addressing (canonical patterns)
    const int ra = lane & 15;                 // A: row within 16
    const int ka = (lane >> 4) * 16;          // A: k byte offset (0 / 16)
    const int rb = (lane & 7) + ((lane >> 4) & 1) * 8;  // B: n-row within 16
    const int kb = ((lane >> 3) & 1) * 16;              // B: k byte offset

    const uint32_t aoffH = sbA_hi + (uint32_t)((wm * 32 + ra) * AB + ka);
    const uint32_t aoffL = sbA_lo + (uint32_t)((wm * 32 + ra) * AB + ka);
    const uint32_t boff  = sbW + (uint32_t)((wn * 64 + rb) * AB + kb);

    const int ntiles = N_EDGES / 128;  // 6250 exact
    for (int tile = blockIdx.x; tile < ntiles; tile += gridDim.x) {
        __syncthreads();  // prior epilogue done before overwriting idx / A
        const int e0 = tile * 128;
        if (t < 128) {
            int2 p = *reinterpret_cast<const int2*>(&eidx[(size_t)(e0 + t) * 2]);
            sSrc[t] = p.x; sDst[t] = p.y;
            atomicAdd(&g_counts[p.x], 1.0f);
        }

        // Load + hi/lo split A tile: 128 rows x 128 k fp32 -> bf16
        #pragma unroll
        for (int i = 0; i < 16; i++) {
            int idx = t + i * 256;
            int row = idx >> 5, q = idx & 31;     // q indexes groups of 4 k
            float4 v = *reinterpret_cast<const float4*>(
                &ef[(size_t)(e0 + row) * 128 + q * 4]);
            __nv_bfloat16 h0 = __float2bfloat16(v.x), h1 = __float2bfloat16(v.y);
            __nv_bfloat16 h2 = __float2bfloat16(v.z), h3 = __float2bfloat16(v.w);
            __nv_bfloat16 l0 = __float2bfloat16(v.x - __bfloat162float(h0));
            __nv_bfloat16 l1 = __float2bfloat16(v.y - __bfloat162float(h1));
            __nv_bfloat16 l2 = __float2bfloat16(v.z - __bfloat162float(h2));
            __nv_bfloat16 l3 = __float2bfloat16(v.w - __bfloat162float(h3));
            uint32_t off = (uint32_t)(row * AB + q * 8);
            *reinterpret_cast<uint2*>(sA_hi + off) = make_uint2(pack_bf16(h0, h1), pack_bf16(h2, h3));
            *reinterpret_cast<uint2*>(sA_lo + off) = make_uint2(pack_bf16(l0, l1), pack_bf16(l2, l3));
        }
        __syncthreads();

        float ag[2][8][4], af[2][8][4];
        #pragma unroll
        for (int mt = 0; mt < 2; mt++)
            #pragma unroll
            for (int nt = 0; nt < 8; nt++)
                #pragma unroll
                for (int i = 0; i < 4; i++) { ag[mt][nt][i] = 0.f; af[mt][nt][i] = 0.f; }

        #pragma unroll
        for (int ks = 0; ks < 8; ks++) {
            uint32_t ah[2][4], al[2][4];
            ldsm_x4(ah[0], aoffH + ks * 32);
            ldsm_x4(ah[1], aoffH + 16 * AB + ks * 32);
            ldsm_x4(al[0], aoffL + ks * 32);
            ldsm_x4(al[1], aoffL + 16 * AB + ks * 32);

            #pragma unroll
            for (int m = 0; m < 2; m++) {
                float (*acc)[8][4] = m ? af : ag;
                uint32_t bufH = boff + (uint32_t)(m * 2 * WBUF);
                uint32_t bufL = bufH + WBUF;
                uint32_t bh[16], bl[16];
                #pragma unroll
                for (int np = 0; np < 4; np++) {  // pairs of n8 tiles
                    ldsm_x4(&bh[np * 4], bufH + (uint32_t)(np * 16 * AB) + ks * 32);
                    ldsm_x4(&bl[np * 4], bufL + (uint32_t)(np * 16 * AB) + ks * 32);
                }
                #pragma unroll
                for (int mt = 0; mt < 2; mt++)
                    #pragma unroll
                    for (int nt = 0; nt < 8; nt++) {
                        mma_bf16(acc[mt][nt], ah[mt], &bh[nt * 2]);   // Ahi * Bhi
                        mma_bf16(acc[mt][nt], al[mt], &bh[nt * 2]);   // Alo * Bhi
                        mma_bf16(acc[mt][nt], ah[mt], &bl[nt * 2]);   // Ahi * Blo
                    }
            }
        }

        // Epilogue: thread owns rows wm*32 + mt*16 + (lane>>2) (+8), cols
        // wn*64 + nt*8 + (lane&3)*2 (+1).
        #pragma unroll
        for (int mt = 0; mt < 2; mt++) {
            #pragma unroll
            for (int rr = 0; rr < 2; rr++) {
                const int row = wm * 32 + mt * 16 + (lane >> 2) + rr * 8;
                const int dst = sDst[row], src = sSrc[row];
                const float* hp = &g_hidden[(size_t)dst * 128];
                float* op = &out[(size_t)src * 128];
                #pragma unroll
                for (int nt = 0; nt < 8; nt++) {
                    const int c = wn * 64 + nt * 8 + (lane & 3) * 2;
                    float2 nb = *reinterpret_cast<const float2*>(hp + c);
                    float gx = ag[mt][nt][rr * 2 + 0] + sBg[c];
                    float gy = ag[mt][nt][rr * 2 + 1] + sBg[c + 1];
                    float g0 = __fdividef(1.f, 1.f + __expf(-gx));
                    float g1 = __fdividef(1.f, 1.f + __expf(-gy));
                    float m0 = g0 * (af[mt][nt][rr * 2 + 0] + sBf[c])     * nb.x;
                    float m1 = g1 * (af[mt][nt][rr * 2 + 1] + sBf[c + 1]) * nb.y;
                    red_add_v2(op + c, m0, m1);
                }
            }
        }
    }
}

// ---------------------------------------------------------------------------
// K3: finalize — out = relu(bn(hidden + sums/max(counts,1)))
// ---------------------------------------------------------------------------
__global__ void finalize_kernel(const float* __restrict__ gamma,
                                const float* __restrict__ beta,
                                const float* __restrict__ mean,
                                const float* __restrict__ var,
                                float* __restrict__ out) {
    int idx = blockIdx.x * blockDim.x + threadIdx.x;
    const int total = N_NODES * 32;
    if (idx >= total) return;
    int node = idx >> 5;
    int q    = idx & 31;
    float inv = 1.f / fmaxf(g_counts[node], 1.f);

    float4 s  = reinterpret_cast<float4*>(out)[idx];
    float4 h  = *reinterpret_cast<const float4*>(&g_hidden[node * D + q * 4]);
    float4 mu = *reinterpret_cast<const float4*>(&mean[q * 4]);
    float4 vr = *reinterpret_cast<const float4*>(&var[q * 4]);
    float4 ga = *reinterpret_cast<const float4*>(&gamma[q * 4]);
    float4 be = *reinterpret_cast<const float4*>(&beta[q * 4]);

    float4 o;
    o.x = fmaxf((h.x + s.x * inv - mu.x) * rsqrtf(vr.x + BN_EPS) * ga.x + be.x, 0.f);
    o.y = fmaxf((h.y + s.y * inv - mu.y) * rsqrtf(vr.y + BN_EPS) * ga.y + be.y, 0.f);
    o.z = fmaxf((h.z + s.z * inv - mu.z) * rsqrtf(vr.z + BN_EPS) * ga.z + be.z, 0.f);
    o.w = fmaxf((h.w + s.w * inv - mu.w) * rsqrtf(vr.w + BN_EPS) * ga.w + be.w, 0.f);
    reinterpret_cast<float4*>(out)[idx] = o;
}

// ---------------------------------------------------------------------------
// launch
// ---------------------------------------------------------------------------
extern "C" void kernel_launch(void* const* d_in, const int* in_sizes, int n_in,
                              void* d_out, int out_size) {
    const float* nf    = (const float*)d_in[0];
    const float* ef    = (const float*)d_in[1];
    const float* Wn    = (const float*)d_in[2];
    const float* bn_   = (const float*)d_in[3];
    const float* Wg    = (const float*)d_in[4];
    const float* bg    = (const float*)d_in[5];
    const float* Wf    = (const float*)d_in[6];
    const float* bf    = (const float*)d_in[7];
    const float* gamma = (const float*)d_in[8];
    const float* beta  = (const float*)d_in[9];
    const float* mean  = (const float*)d_in[10];
    const float* var   = (const float*)d_in[11];
    const int*   eidx  = (const int*)d_in[12];
    float* out = (float*)d_out;

    const int node_smem = (128 * PAD + NT * PAD) * (int)sizeof(float);

    int dev = 0, nsm = 148;
    cudaGetDevice(&dev);
    cudaDeviceGetAttribute(&nsm, cudaDevAttrMultiProcessorCount, dev);
    cudaFuncSetAttribute(node_gemm_kernel, cudaFuncAttributeMaxDynamicSharedMemorySize, node_smem);
    cudaFuncSetAttribute(edge_kernel,      cudaFuncAttributeMaxDynamicSharedMemorySize, EK_SMEM);

    zero_kernel<<<512, 256>>>(out);
    node_gemm_kernel<<<2 * nsm, 256, node_smem>>>(nf, Wn, bn_);
    edge_kernel<<<nsm, 256, EK_SMEM>>>(ef, Wg, bg, Wf, bf, eidx, out);
    finalize_kernel<<<(N_NODES * 32 + 255) / 256, 256>>>(gamma, beta, mean, var, out);
}

// round 5
// speedup vs baseline: 2.2246x; 1.3876x over previous
#include <cuda_runtime.h>
#include <cuda_fp16.h>
#include <cstdint>

#define N_NODES 50000
#define N_EDGES 800000
#define D 128
#define BN_EPS 1e-3f

#define NT 64          // nodes per tile (node gemm)
#define PAD 132        // node gemm smem padding

#define PK 136         // fp16 elements per smem row (pitch), 272 B
#define AB 272         // bytes per smem row
#define WBUF 34816     // bytes per 128x136 fp16 buffer

// Scratch
__device__ float g_hidden[N_NODES * D];
__device__ float g_counts[N_NODES];

// ---------------------------------------------------------------------------
// helpers
// ---------------------------------------------------------------------------
__device__ __forceinline__ uint32_t smem_u32(const void* p) {
    uint32_t a;
    asm("{ .reg .u64 t; cvta.to.shared.u64 t, %1; cvt.u32.u64 %0, t; }" : "=r"(a) : "l"(p));
    return a;
}

__device__ __forceinline__ void red_add_v2(float* addr, float a, float b) {
    asm volatile("red.global.add.v2.f32 [%0], {%1, %2};"
                 :: "l"(addr), "f"(a), "f"(b) : "memory");
}

__device__ __forceinline__ void ldsm_x4(uint32_t* r, uint32_t addr) {
    asm volatile("ldmatrix.sync.aligned.m8n8.x4.shared.b16 {%0,%1,%2,%3}, [%4];"
                 : "=r"(r[0]), "=r"(r[1]), "=r"(r[2]), "=r"(r[3]) : "r"(addr));
}

__device__ __forceinline__ void mma_fp16(float* c, const uint32_t* a, const uint32_t* b) {
    asm volatile("mma.sync.aligned.m16n8k16.row.col.f32.f16.f16.f32 "
                 "{%0,%1,%2,%3}, {%4,%5,%6,%7}, {%8,%9}, {%0,%1,%2,%3};"
                 : "+f"(c[0]), "+f"(c[1]), "+f"(c[2]), "+f"(c[3])
                 : "r"(a[0]), "r"(a[1]), "r"(a[2]), "r"(a[3]), "r"(b[0]), "r"(b[1]));
}

__device__ __forceinline__ uint32_t pack_h2(__half lo, __half hi) {
    return (uint32_t)__half_as_ushort(lo) | ((uint32_t)__half_as_ushort(hi) << 16);
}

// ---------------------------------------------------------------------------
// K0: zero accumulator + counts
// ---------------------------------------------------------------------------
__global__ void zero_kernel(float* __restrict__ out) {
    int idx = blockIdx.x * blockDim.x + threadIdx.x;
    int stride = gridDim.x * blockDim.x;
    const int nv4 = N_NODES * D / 4;
    float4 z = make_float4(0.f, 0.f, 0.f, 0.f);
    for (int i = idx; i < nv4; i += stride)
        reinterpret_cast<float4*>(out)[i] = z;
    for (int i = idx; i < N_NODES; i += stride)
        g_counts[i] = 0.f;
}

// ---------------------------------------------------------------------------
// K1: node_hidden = nf @ W_node + b_node  (fp32, exact)
// ---------------------------------------------------------------------------
__global__ __launch_bounds__(256, 2)
void node_gemm_kernel(const float* __restrict__ nf,
                      const float* __restrict__ W,
                      const float* __restrict__ b) {
    extern __shared__ float sm[];
    float* sW = sm;
    float* sX = sm + 128 * PAD;
    const int t = threadIdx.x, tx = t & 31, ty = t >> 5;

    for (int i = t; i < 128 * 32; i += 256) {
        int r = i >> 5, q = i & 31;
        *reinterpret_cast<float4*>(&sW[r * PAD + q * 4]) =
            *reinterpret_cast<const float4*>(&W[r * D + q * 4]);
    }
    float4 bb = *reinterpret_cast<const float4*>(&b[tx * 4]);

    const int ntiles = (N_NODES + NT - 1) / NT;
    for (int tile = blockIdx.x; tile < ntiles; tile += gridDim.x) {
        __syncthreads();
        const int row0 = tile * NT;
        for (int i = t; i < NT * 32; i += 256) {
            int r = i >> 5, q = i & 31;
            int row = row0 + r;
            float4 v = make_float4(0.f, 0.f, 0.f, 0.f);
            if (row < N_NODES)
                v = *reinterpret_cast<const float4*>(&nf[row * D + q * 4]);
            *reinterpret_cast<float4*>(&sX[r * PAD + q * 4]) = v;
        }
        __syncthreads();

        float acc[8][4];
        #pragma unroll
        for (int i = 0; i < 8; i++)
            #pragma unroll
            for (int c = 0; c < 4; c++) acc[i][c] = 0.f;

        #pragma unroll 4
        for (int k4 = 0; k4 < 32; k4++) {
            float ev[8][4];
            #pragma unroll
            for (int i = 0; i < 8; i++) {
                float4 v = *reinterpret_cast<float4*>(&sX[(ty * 8 + i) * PAD + k4 * 4]);
                ev[i][0] = v.x; ev[i][1] = v.y; ev[i][2] = v.z; ev[i][3] = v.w;
            }
            #pragma unroll
            for (int kk = 0; kk < 4; kk++) {
                float4 w = *reinterpret_cast<float4*>(&sW[(k4 * 4 + kk) * PAD + tx * 4]);
                #pragma unroll
                for (int i = 0; i < 8; i++) {
                    float e = ev[i][kk];
                    acc[i][0] += e * w.x; acc[i][1] += e * w.y;
                    acc[i][2] += e * w.z; acc[i][3] += e * w.w;
                }
            }
        }
        #pragma unroll
        for (int i = 0; i < 8; i++) {
            int row = row0 + ty * 8 + i;
            if (row < N_NODES) {
                float4 o;
                o.x = acc[i][0] + bb.x; o.y = acc[i][1] + bb.y;
                o.z = acc[i][2] + bb.z; o.w = acc[i][3] + bb.w;
                *reinterpret_cast<float4*>(&g_hidden[row * D + tx * 4]) = o;
            }
        }
    }
}

// ---------------------------------------------------------------------------
// K2: edge kernel — fp16 single-pass mma.sync GEMMs (gate & filt) + epilogue
//
// Tile: M=128 edges x N=128 x K=128 per CTA iteration. Persistent CTAs.
// SMEM layout (bytes):
//   [0]     sSrc[128]  [512] sDst[128]  [1024] sBg[128]  [1536] sBf[128]
//   [2048]  A   [128][PK] fp16          (34816)
//   [36864] Wg^T [n=128][k=PK] fp16     (34816)
//   [71680] Wf^T [n=128][k=PK] fp16     (34816)
// total 106496.  1 CTA/SM, 256 threads.
//
// Warp grid 4(M) x 2(N): warp tile 32x64. Per warp: 2 m16 x 8 n8 c-tiles,
// 1 fp16 mma per c-tile per k16 per matrix -> 256 HMMA/warp/tile (3x fewer
// than the R4 bf16x3 split).
// ---------------------------------------------------------------------------
#define EK_SMEM 106496
#define OFF_A   2048
#define OFF_W   36864

__global__ __launch_bounds__(256, 1)
void edge_kernel(const float* __restrict__ ef,
                 const float* __restrict__ Wg, const float* __restrict__ bgp,
                 const float* __restrict__ Wf, const float* __restrict__ bfp,
                 const int*   __restrict__ eidx,
                 float* __restrict__ out) {
    extern __shared__ __align__(16) char smem[];
    int*   sSrc = reinterpret_cast<int*>(smem);
    int*   sDst = reinterpret_cast<int*>(smem + 512);
    float* sBg  = reinterpret_cast<float*>(smem + 1024);
    float* sBf  = reinterpret_cast<float*>(smem + 1536);
    char*  sA   = smem + OFF_A;
    char*  sW   = smem + OFF_W;

    const int t = threadIdx.x, w = t >> 5, lane = t & 31;
    const int wm = w & 3, wn = w >> 2;

    if (t < 128) { sBg[t] = bgp[t]; sBf[t] = bfp[t]; }

    // One-time: load + transpose W matrices into resident SMEM as fp16
    for (int m = 0; m < 2; m++) {
        const float* W = m ? Wf : Wg;
        char* buf = sW + m * WBUF;
        for (int idx = t; idx < 16384; idx += 256) {
            int k = idx >> 7, n = idx & 127;
            *reinterpret_cast<__half*>(buf + n * AB + k * 2) = __float2half_rn(W[idx]);
        }
    }
    __syncthreads();

    const uint32_t sbA = smem_u32(sA);
    const uint32_t sbW = smem_u32(sW);

    // ldmatrix lane addressing (canonical patterns)
    const int ra = lane & 15;                 // A: row within 16
    const int ka = (lane >> 4) * 16;          // A: k byte offset (0 / 16)
    const int rb = (lane & 7) + ((lane >> 4) & 1) * 8;  // B: n-row within 16
    const int kb = ((lane >> 3) & 1) * 16;              // B: k byte offset

    const uint32_t aoff = sbA + (uint32_t)((wm * 32 + ra) * AB + ka);
    const uint32_t boff = sbW + (uint32_t)((wn * 64 + rb) * AB + kb);

    const int ntiles = N_EDGES / 128;  // 6250 exact
    for (int tile = blockIdx.x; tile < ntiles; tile += gridDim.x) {
        __syncthreads();  // prior epilogue done before overwriting idx / A
        const int e0 = tile * 128;
        if (t < 128) {
            int2 p = *reinterpret_cast<const int2*>(&eidx[(size_t)(e0 + t) * 2]);
            sSrc[t] = p.x; sDst[t] = p.y;
            atomicAdd(&g_counts[p.x], 1.0f);
        }

        // Load A tile: 128 rows x 128 k fp32 -> fp16
        #pragma unroll
        for (int i = 0; i < 16; i++) {
            int idx = t + i * 256;
            int row = idx >> 5, q = idx & 31;     // q indexes groups of 4 k
            float4 v = *reinterpret_cast<const float4*>(
                &ef[(size_t)(e0 + row) * 128 + q * 4]);
            uint32_t off = (uint32_t)(row * AB + q * 8);
            *reinterpret_cast<uint2*>(sA + off) = make_uint2(
                pack_h2(__float2half_rn(v.x), __float2half_rn(v.y)),
                pack_h2(__float2half_rn(v.z), __float2half_rn(v.w)));
        }
        __syncthreads();

        float ag[2][8][4], af[2][8][4];
        #pragma unroll
        for (int mt = 0; mt < 2; mt++)
            #pragma unroll
            for (int nt = 0; nt < 8; nt++)
                #pragma unroll
                for (int i = 0; i < 4; i++) { ag[mt][nt][i] = 0.f; af[mt][nt][i] = 0.f; }

        #pragma unroll
        for (int ks = 0; ks < 8; ks++) {
            uint32_t ah[2][4];
            ldsm_x4(ah[0], aoff + ks * 32);
            ldsm_x4(ah[1], aoff + 16 * AB + ks * 32);

            #pragma unroll
            for (int m = 0; m < 2; m++) {
                float (*acc)[8][4] = m ? af : ag;
                uint32_t buf = boff + (uint32_t)(m * WBUF);
                uint32_t bh[16];
                #pragma unroll
                for (int np = 0; np < 4; np++)   // pairs of n8 tiles
                    ldsm_x4(&bh[np * 4], buf + (uint32_t)(np * 16 * AB) + ks * 32);
                #pragma unroll
                for (int mt = 0; mt < 2; mt++)
                    #pragma unroll
                    for (int nt = 0; nt < 8; nt++)
                        mma_fp16(acc[mt][nt], ah[mt], &bh[nt * 2]);
            }
        }

        // Epilogue: thread owns rows wm*32 + mt*16 + (lane>>2) (+8), cols
        // wn*64 + nt*8 + (lane&3)*2 (+1).
        #pragma unroll
        for (int mt = 0; mt < 2; mt++) {
            #pragma unroll
            for (int rr = 0; rr < 2; rr++) {
                const int row = wm * 32 + mt * 16 + (lane >> 2) + rr * 8;
                const int dst = sDst[row], src = sSrc[row];
                const float* hp = &g_hidden[(size_t)dst * 128];
                float* op = &out[(size_t)src * 128];
                #pragma unroll
                for (int nt = 0; nt < 8; nt++) {
                    const int c = wn * 64 + nt * 8 + (lane & 3) * 2;
                    float2 nb = *reinterpret_cast<const float2*>(hp + c);
                    float gx = ag[mt][nt][rr * 2 + 0] + sBg[c];
                    float gy = ag[mt][nt][rr * 2 + 1] + sBg[c + 1];
                    float g0 = __fdividef(1.f, 1.f + __expf(-gx));
                    float g1 = __fdividef(1.f, 1.f + __expf(-gy));
                    float m0 = g0 * (af[mt][nt][rr * 2 + 0] + sBf[c])     * nb.x;
                    float m1 = g1 * (af[mt][nt][rr * 2 + 1] + sBf[c + 1]) * nb.y;
                    red_add_v2(op + c, m0, m1);
                }
            }
        }
    }
}

// ---------------------------------------------------------------------------
// K3: finalize — out = relu(bn(hidden + sums/max(counts,1)))
// ---------------------------------------------------------------------------
__global__ void finalize_kernel(const float* __restrict__ gamma,
                                const float* __restrict__ beta,
                                const float* __restrict__ mean,
                                const float* __restrict__ var,
                                float* __restrict__ out) {
    int idx = blockIdx.x * blockDim.x + threadIdx.x;
    const int total = N_NODES * 32;
    if (idx >= total) return;
    int node = idx >> 5;
    int q    = idx & 31;
    float inv = 1.f / fmaxf(g_counts[node], 1.f);

    float4 s  = reinterpret_cast<float4*>(out)[idx];
    float4 h  = *reinterpret_cast<const float4*>(&g_hidden[node * D + q * 4]);
    float4 mu = *reinterpret_cast<const float4*>(&mean[q * 4]);
    float4 vr = *reinterpret_cast<const float4*>(&var[q * 4]);
    float4 ga = *reinterpret_cast<const float4*>(&gamma[q * 4]);
    float4 be = *reinterpret_cast<const float4*>(&beta[q * 4]);

    float4 o;
    o.x = fmaxf((h.x + s.x * inv - mu.x) * rsqrtf(vr.x + BN_EPS) * ga.x + be.x, 0.f);
    o.y = fmaxf((h.y + s.y * inv - mu.y) * rsqrtf(vr.y + BN_EPS) * ga.y + be.y, 0.f);
    o.z = fmaxf((h.z + s.z * inv - mu.z) * rsqrtf(vr.z + BN_EPS) * ga.z + be.z, 0.f);
    o.w = fmaxf((h.w + s.w * inv - mu.w) * rsqrtf(vr.w + BN_EPS) * ga.w + be.w, 0.f);
    reinterpret_cast<float4*>(out)[idx] = o;
}

// ---------------------------------------------------------------------------
// launch
// ---------------------------------------------------------------------------
extern "C" void kernel_launch(void* const* d_in, const int* in_sizes, int n_in,
                              void* d_out, int out_size) {
    const float* nf    = (const float*)d_in[0];
    const float* ef    = (const float*)d_in[1];
    const float* Wn    = (const float*)d_in[2];
    const float* bn_   = (const float*)d_in[3];
    const float* Wg    = (const float*)d_in[4];
    const float* bg    = (const float*)d_in[5];
    const float* Wf    = (const float*)d_in[6];
    const float* bf    = (const float*)d_in[7];
    const float* gamma = (const float*)d_in[8];
    const float* beta  = (const float*)d_in[9];
    const float* mean  = (const float*)d_in[10];
    const float* var   = (const float*)d_in[11];
    const int*   eidx  = (const int*)d_in[12];
    float* out = (float*)d_out;

    const int node_smem = (128 * PAD + NT * PAD) * (int)sizeof(float);

    int dev = 0, nsm = 148;
    cudaGetDevice(&dev);
    cudaDeviceGetAttribute(&nsm, cudaDevAttrMultiProcessorCount, dev);
    cudaFuncSetAttribute(node_gemm_kernel, cudaFuncAttributeMaxDynamicSharedMemorySize, node_smem);
    cudaFuncSetAttribute(edge_kernel,      cudaFuncAttributeMaxDynamicSharedMemorySize, EK_SMEM);

    zero_kernel<<<512, 256>>>(out);
    node_gemm_kernel<<<2 * nsm, 256, node_smem>>>(nf, Wn, bn_);
    edge_kernel<<<nsm, 256, EK_SMEM>>>(ef, Wg, bg, Wf, bf, eidx, out);
    finalize_kernel<<<(N_NODES * 32 + 255) / 256, 256>>>(gamma, beta, mean, var, out);
}

// round 8
// speedup vs baseline: 3.2631x; 1.4668x over previous
#include <cuda_runtime.h>
#include <cuda_fp16.h>
#include <cstdint>

#define N_NODES 50000
#define N_EDGES 800000
#define D 128
#define BN_EPS 1e-3f

#define NT 64          // nodes per tile (node gemm)
#define PAD 132        // node gemm smem padding

#define AB 272         // bytes per fp16 smem row (136 fp16, pitch)
#define WBUF 34816     // bytes per 128x136 fp16 buffer
#define SPITCH 544     // stage fp32 row pitch bytes (512 data + 32 pad)

// Scratch
__device__ float g_hidden[N_NODES * D];
__device__ float g_counts[N_NODES];

// ---------------------------------------------------------------------------
// helpers
// ---------------------------------------------------------------------------
__device__ __forceinline__ uint32_t smem_u32(const void* p) {
    uint32_t a;
    asm("{ .reg .u64 t; cvta.to.shared.u64 t, %1; cvt.u32.u64 %0, t; }" : "=r"(a) : "l"(p));
    return a;
}

__device__ __forceinline__ void red_add_v2(float* addr, float a, float b) {
    asm volatile("red.global.add.v2.f32 [%0], {%1, %2};"
                 :: "l"(addr), "f"(a), "f"(b) : "memory");
}

__device__ __forceinline__ void ldsm_x4(uint32_t* r, uint32_t addr) {
    asm volatile("ldmatrix.sync.aligned.m8n8.x4.shared.b16 {%0,%1,%2,%3}, [%4];"
                 : "=r"(r[0]), "=r"(r[1]), "=r"(r[2]), "=r"(r[3]) : "r"(addr));
}

__device__ __forceinline__ void mma_fp16(float* c, const uint32_t* a, const uint32_t* b) {
    asm volatile("mma.sync.aligned.m16n8k16.row.col.f32.f16.f16.f32 "
                 "{%0,%1,%2,%3}, {%4,%5,%6,%7}, {%8,%9}, {%0,%1,%2,%3};"
                 : "+f"(c[0]), "+f"(c[1]), "+f"(c[2]), "+f"(c[3])
                 : "r"(a[0]), "r"(a[1]), "r"(a[2]), "r"(a[3]), "r"(b[0]), "r"(b[1]));
}

__device__ __forceinline__ uint32_t pack_h2(__half lo, __half hi) {
    return (uint32_t)__half_as_ushort(lo) | ((uint32_t)__half_as_ushort(hi) << 16);
}

__device__ __forceinline__ float tanh_fast(float x) {
    float y; asm("tanh.approx.f32 %0, %1;" : "=f"(y) : "f"(x)); return y;
}
__device__ __forceinline__ float sigmoid_fast(float x) {
    return fmaf(tanh_fast(0.5f * x), 0.5f, 0.5f);
}

__device__ __forceinline__ void cp16(uint32_t saddr, const void* g) {
    asm volatile("cp.async.cg.shared.global [%0], [%1], 16;" :: "r"(saddr), "l"(g));
}
#define CP_COMMIT() asm volatile("cp.async.commit_group;" ::: "memory")
#define CP_WAIT0()  asm volatile("cp.async.wait_group 0;" ::: "memory")

// ---------------------------------------------------------------------------
// K0: zero accumulator + counts
// ---------------------------------------------------------------------------
__global__ void zero_kernel(float* __restrict__ out) {
    int idx = blockIdx.x * blockDim.x + threadIdx.x;
    int stride = gridDim.x * blockDim.x;
    const int nv4 = N_NODES * D / 4;
    float4 z = make_float4(0.f, 0.f, 0.f, 0.f);
    for (int i = idx; i < nv4; i += stride)
        reinterpret_cast<float4*>(out)[i] = z;
    for (int i = idx; i < N_NODES; i += stride)
        g_counts[i] = 0.f;
}

// ---------------------------------------------------------------------------
// K1: node_hidden = nf @ W_node + b_node  (fp32, exact)
// ---------------------------------------------------------------------------
__global__ __launch_bounds__(256, 2)
void node_gemm_kernel(const float* __restrict__ nf,
                      const float* __restrict__ W,
                      const float* __restrict__ b) {
    extern __shared__ float sm[];
    float* sW = sm;
    float* sX = sm + 128 * PAD;
    const int t = threadIdx.x, tx = t & 31, ty = t >> 5;

    for (int i = t; i < 128 * 32; i += 256) {
        int r = i >> 5, q = i & 31;
        *reinterpret_cast<float4*>(&sW[r * PAD + q * 4]) =
            *reinterpret_cast<const float4*>(&W[r * D + q * 4]);
    }
    float4 bb = *reinterpret_cast<const float4*>(&b[tx * 4]);

    const int ntiles = (N_NODES + NT - 1) / NT;
    for (int tile = blockIdx.x; tile < ntiles; tile += gridDim.x) {
        __syncthreads();
        const int row0 = tile * NT;
        for (int i = t; i < NT * 32; i += 256) {
            int r = i >> 5, q = i & 31;
            int row = row0 + r;
            float4 v = make_float4(0.f, 0.f, 0.f, 0.f);
            if (row < N_NODES)
                v = *reinterpret_cast<const float4*>(&nf[row * D + q * 4]);
            *reinterpret_cast<float4*>(&sX[r * PAD + q * 4]) = v;
        }
        __syncthreads();

        float acc[8][4];
        #pragma unroll
        for (int i = 0; i < 8; i++)
            #pragma unroll
            for (int c = 0; c < 4; c++) acc[i][c] = 0.f;

        #pragma unroll 4
        for (int k4 = 0; k4 < 32; k4++) {
            float ev[8][4];
            #pragma unroll
            for (int i = 0; i < 8; i++) {
                float4 v = *reinterpret_cast<float4*>(&sX[(ty * 8 + i) * PAD + k4 * 4]);
                ev[i][0] = v.x; ev[i][1] = v.y; ev[i][2] = v.z; ev[i][3] = v.w;
            }
            #pragma unroll
            for (int kk = 0; kk < 4; kk++) {
                float4 w = *reinterpret_cast<float4*>(&sW[(k4 * 4 + kk) * PAD + tx * 4]);
                #pragma unroll
                for (int i = 0; i < 8; i++) {
                    float e = ev[i][kk];
                    acc[i][0] += e * w.x; acc[i][1] += e * w.y;
                    acc[i][2] += e * w.z; acc[i][3] += e * w.w;
                }
            }
        }
        #pragma unroll
        for (int i = 0; i < 8; i++) {
            int row = row0 + ty * 8 + i;
            if (row < N_NODES) {
                float4 o;
                o.x = acc[i][0] + bb.x; o.y = acc[i][1] + bb.y;
                o.z = acc[i][2] + bb.z; o.w = acc[i][3] + bb.w;
                *reinterpret_cast<float4*>(&g_hidden[row * D + tx * 4]) = o;
            }
        }
    }
}

// ---------------------------------------------------------------------------
// K2: edge kernel — fp16 mma.sync + cp.async pipelined stage + fused epilogue
//
// 512 threads, 16 warps: grid 4(M) x 4(N), warp tile 32x32.
// SMEM layout (bytes):
//   [0]      sSrc[128]  [512] sDst[128]  [1024] sBg[128]  [1536] sBf[128]
//   [2048]   A fp16 [128][136]                (34816)
//   [36864]  Wg^T [n=128][k=136] fp16         (34816)
//   [71680]  Wf^T                              (34816)
//   [106496] stage fp32 [128][SPITCH=544B]    (69632)
// total 176128.  1 CTA/SM.
//
// Pipeline per tile i:
//   sync; idx LDG; convert stage(i) -> A fp16; sync;
//   cp.async stage <- tile i+grid; commit;
//   mma; epilogue; cp.async.wait_group 0; (loop -> sync)
// ---------------------------------------------------------------------------
#define EK_SMEM 176128
#define OFF_A   2048
#define OFF_W   36864
#define OFF_S   106496

__global__ __launch_bounds__(512, 1)
void edge_kernel(const float* __restrict__ ef,
                 const float* __restrict__ Wg, const float* __restrict__ bgp,
                 const float* __restrict__ Wf, const float* __restrict__ bfp,
                 const int*   __restrict__ eidx,
                 float* __restrict__ out) {
    extern __shared__ __align__(16) char smem[];
    int*   sSrc = reinterpret_cast<int*>(smem);
    int*   sDst = reinterpret_cast<int*>(smem + 512);
    float* sBg  = reinterpret_cast<float*>(smem + 1024);
    float* sBf  = reinterpret_cast<float*>(smem + 1536);
    char*  sA   = smem + OFF_A;
    char*  sW   = smem + OFF_W;
    char*  sS   = smem + OFF_S;

    const int t = threadIdx.x, w = t >> 5, lane = t & 31;
    const int wm = w & 3, wn = w >> 2;

    const uint32_t sbA = smem_u32(sA);
    const uint32_t sbW = smem_u32(sW);
    const uint32_t sbS = smem_u32(sS);

    const int ntiles = N_EDGES / 128;  // 6250 exact
    const int tile0 = blockIdx.x;

    // Prefetch first tile's raw fp32 into stage (8 x 16B per thread)
    {
        const int e0 = tile0 * 128;
        #pragma unroll
        for (int i = 0; i < 8; i++) {
            int idx = t + i * 512;
            int row = idx >> 5, c16 = idx & 31;
            cp16(sbS + (uint32_t)(row * SPITCH + c16 * 16),
                 &ef[(size_t)(e0 + row) * 128 + c16 * 4]);
        }
        CP_COMMIT();
    }

    if (t < 128) { sBg[t] = bgp[t]; sBf[t] = bfp[t]; }

    // One-time: load + transpose W matrices into resident SMEM as fp16
    for (int m = 0; m < 2; m++) {
        const float* W = m ? Wf : Wg;
        char* buf = sW + m * WBUF;
        for (int idx = t; idx < 16384; idx += 512) {
            int k = idx >> 7, n = idx & 127;
            *reinterpret_cast<__half*>(buf + n * AB + k * 2) = __float2half_rn(W[idx]);
        }
    }
    CP_WAIT0();
    __syncthreads();

    // ldmatrix lane addressing (canonical patterns)
    const int ra = lane & 15;
    const int ka = (lane >> 4) * 16;
    const int rb = (lane & 7) + ((lane >> 4) & 1) * 8;
    const int kb = ((lane >> 3) & 1) * 16;

    const uint32_t aoff = sbA + (uint32_t)((wm * 32 + ra) * AB + ka);
    const uint32_t boff = sbW + (uint32_t)((wn * 32 + rb) * AB + kb);

    for (int tile = tile0; tile < ntiles; tile += gridDim.x) {
        const int e0 = tile * 128;
        if (t < 128) {
            int2 p = *reinterpret_cast<const int2*>(&eidx[(size_t)(e0 + t) * 2]);
            sSrc[t] = p.x; sDst[t] = p.y;
            atomicAdd(&g_counts[p.x], 1.0f);
        }

        // Convert stage fp32 -> A fp16 (per thread: 8 chunks of 4 floats; whole
        // warp shares a row -> conflict-free LDS.128 / STS.64)
        #pragma unroll
        for (int i = 0; i < 8; i++) {
            int idx = t + i * 512;
            int row = idx >> 5, c16 = idx & 31;
            float4 v = *reinterpret_cast<const float4*>(sS + row * SPITCH + c16 * 16);
            *reinterpret_cast<uint2*>(sA + row * AB + c16 * 8) = make_uint2(
                pack_h2(__float2half_rn(v.x), __float2half_rn(v.y)),
                pack_h2(__float2half_rn(v.z), __float2half_rn(v.w)));
        }
        __syncthreads();   // A + idx ready; stage fully consumed

        // Kick prefetch of next tile into stage (overlaps mma+epilogue)
        {
            int tn = tile + gridDim.x;
            if (tn >= ntiles) tn = tile;   // harmless re-fetch on last iter
            const int en = tn * 128;
            #pragma unroll
            for (int i = 0; i < 8; i++) {
                int idx = t + i * 512;
                int row = idx >> 5, c16 = idx & 31;
                cp16(sbS + (uint32_t)(row * SPITCH + c16 * 16),
                     &ef[(size_t)(en + row) * 128 + c16 * 4]);
            }
            CP_COMMIT();
        }

        // mma: acc[m][mt][nt][4]
        float acc[2][2][4][4];
        #pragma unroll
        for (int m = 0; m < 2; m++)
            #pragma unroll
            for (int mt = 0; mt < 2; mt++)
                #pragma unroll
                for (int nt = 0; nt < 4; nt++)
                    #pragma unroll
                    for (int i = 0; i < 4; i++) acc[m][mt][nt][i] = 0.f;

        #pragma unroll
        for (int ks = 0; ks < 8; ks++) {
            uint32_t ah[2][4];
            ldsm_x4(ah[0], aoff + ks * 32);
            ldsm_x4(ah[1], aoff + 16 * AB + ks * 32);
            #pragma unroll
            for (int m = 0; m < 2; m++) {
                uint32_t buf = boff + (uint32_t)(m * WBUF);
                uint32_t bh[8];
                ldsm_x4(&bh[0], buf + ks * 32);
                ldsm_x4(&bh[4], buf + (uint32_t)(16 * AB) + ks * 32);
                #pragma unroll
                for (int mt = 0; mt < 2; mt++)
                    #pragma unroll
                    for (int nt = 0; nt < 4; nt++)
                        mma_fp16(acc[m][mt][nt], ah[mt], &bh[nt * 2]);
            }
        }

        // Epilogue: rows wm*32 + mt*16 + (lane>>2) + rr*8,
        //           cols wn*32 + nt*8 + (lane&3)*2
        #pragma unroll
        for (int mt = 0; mt < 2; mt++) {
            #pragma unroll
            for (int rr = 0; rr < 2; rr++) {
                const int row = wm * 32 + mt * 16 + (lane >> 2) + rr * 8;
                const int dst = sDst[row], src = sSrc[row];
                const float* hp = &g_hidden[(size_t)dst * 128];
                float* op = &out[(size_t)src * 128];
                #pragma unroll
                for (int nt = 0; nt < 4; nt++) {
                    const int c = wn * 32 + nt * 8 + (lane & 3) * 2;
                    float2 nb = *reinterpret_cast<const float2*>(hp + c);
                    float g0 = sigmoid_fast(acc[0][mt][nt][rr * 2 + 0] + sBg[c]);
                    float g1 = sigmoid_fast(acc[0][mt][nt][rr * 2 + 1] + sBg[c + 1]);
                    float m0 = g0 * (acc[1][mt][nt][rr * 2 + 0] + sBf[c])     * nb.x;
                    float m1 = g1 * (acc[1][mt][nt][rr * 2 + 1] + sBf[c + 1]) * nb.y;
                    red_add_v2(op + c, m0, m1);
                }
            }
        }

        CP_WAIT0();        // next tile's stage landed
        __syncthreads();   // everyone done with A/idx/stage before next iter
    }
}

// ---------------------------------------------------------------------------
// K3: finalize — out = relu(bn(hidden + sums/max(counts,1)))
// ---------------------------------------------------------------------------
__global__ void finalize_kernel(const float* __restrict__ gamma,
                                const float* __restrict__ beta,
                                const float* __restrict__ mean,
                                const float* __restrict__ var,
                                float* __restrict__ out) {
    int idx = blockIdx.x * blockDim.x + threadIdx.x;
    const int total = N_NODES * 32;
    if (idx >= total) return;
    int node = idx >> 5;
    int q    = idx & 31;
    float inv = 1.f / fmaxf(g_counts[node], 1.f);

    float4 s  = reinterpret_cast<float4*>(out)[idx];
    float4 h  = *reinterpret_cast<const float4*>(&g_hidden[node * D + q * 4]);
    float4 mu = *reinterpret_cast<const float4*>(&mean[q * 4]);
    float4 vr = *reinterpret_cast<const float4*>(&var[q * 4]);
    float4 ga = *reinterpret_cast<const float4*>(&gamma[q * 4]);
    float4 be = *reinterpret_cast<const float4*>(&beta[q * 4]);

    float4 o;
    o.x = fmaxf((h.x + s.x * inv - mu.x) * rsqrtf(vr.x + BN_EPS) * ga.x + be.x, 0.f);
    o.y = fmaxf((h.y + s.y * inv - mu.y) * rsqrtf(vr.y + BN_EPS) * ga.y + be.y, 0.f);
    o.z = fmaxf((h.z + s.z * inv - mu.z) * rsqrtf(vr.z + BN_EPS) * ga.z + be.z, 0.f);
    o.w = fmaxf((h.w + s.w * inv - mu.w) * rsqrtf(vr.w + BN_EPS) * ga.w + be.w, 0.f);
    reinterpret_cast<float4*>(out)[idx] = o;
}

// ---------------------------------------------------------------------------
// launch
// ---------------------------------------------------------------------------
extern "C" void kernel_launch(void* const* d_in, const int* in_sizes, int n_in,
                              void* d_out, int out_size) {
    const float* nf    = (const float*)d_in[0];
    const float* ef    = (const float*)d_in[1];
    const float* Wn    = (const float*)d_in[2];
    const float* bn_   = (const float*)d_in[3];
    const float* Wg    = (const float*)d_in[4];
    const float* bg    = (const float*)d_in[5];
    const float* Wf    = (const float*)d_in[6];
    const float* bf    = (const float*)d_in[7];
    const float* gamma = (const float*)d_in[8];
    const float* beta  = (const float*)d_in[9];
    const float* mean  = (const float*)d_in[10];
    const float* var   = (const float*)d_in[11];
    const int*   eidx  = (const int*)d_in[12];
    float* out = (float*)d_out;

    const int node_smem = (128 * PAD + NT * PAD) * (int)sizeof(float);

    int dev = 0, nsm = 148;
    cudaGetDevice(&dev);
    cudaDeviceGetAttribute(&nsm, cudaDevAttrMultiProcessorCount, dev);
    cudaFuncSetAttribute(node_gemm_kernel, cudaFuncAttributeMaxDynamicSharedMemorySize, node_smem);
    cudaFuncSetAttribute(edge_kernel,      cudaFuncAttributeMaxDynamicSharedMemorySize, EK_SMEM);

    zero_kernel<<<512, 256>>>(out);
    node_gemm_kernel<<<2 * nsm, 256, node_smem>>>(nf, Wn, bn_);
    edge_kernel<<<nsm, 512, EK_SMEM>>>(ef, Wg, bg, Wf, bf, eidx, out);
    finalize_kernel<<<(N_NODES * 32 + 255) / 256, 256>>>(gamma, beta, mean, var, out);
}

// round 9
// speedup vs baseline: 3.3774x; 1.0350x over previous
#include <cuda_runtime.h>
#include <cuda_fp16.h>
#include <cstdint>

#define N_NODES 50000
#define N_EDGES 800000
#define D 128
#define BN_EPS 1e-3f

#define NT 64          // nodes per tile (node gemm)
#define PAD 132        // node gemm smem padding

#define AB 272         // bytes per fp16 smem row (136 fp16, pitch)
#define WBUF 34816     // bytes per 128x136 fp16 buffer
#define SPITCH 544     // stage fp32 row pitch bytes (512 data + 32 pad)

// Scratch
__device__ float g_hidden[N_NODES * D];
__device__ float g_counts[N_NODES];

// ---------------------------------------------------------------------------
// helpers
// ---------------------------------------------------------------------------
__device__ __forceinline__ uint32_t smem_u32(const void* p) {
    uint32_t a;
    asm("{ .reg .u64 t; cvta.to.shared.u64 t, %1; cvt.u32.u64 %0, t; }" : "=r"(a) : "l"(p));
    return a;
}

__device__ __forceinline__ void red_add_v2(float* addr, float a, float b) {
    asm volatile("red.global.add.v2.f32 [%0], {%1, %2};"
                 :: "l"(addr), "f"(a), "f"(b) : "memory");
}

__device__ __forceinline__ void ldsm_x4(uint32_t* r, uint32_t addr) {
    asm volatile("ldmatrix.sync.aligned.m8n8.x4.shared.b16 {%0,%1,%2,%3}, [%4];"
                 : "=r"(r[0]), "=r"(r[1]), "=r"(r[2]), "=r"(r[3]) : "r"(addr));
}

__device__ __forceinline__ void mma_fp16(float* c, const uint32_t* a, const uint32_t* b) {
    asm volatile("mma.sync.aligned.m16n8k16.row.col.f32.f16.f16.f32 "
                 "{%0,%1,%2,%3}, {%4,%5,%6,%7}, {%8,%9}, {%0,%1,%2,%3};"
                 : "+f"(c[0]), "+f"(c[1]), "+f"(c[2]), "+f"(c[3])
                 : "r"(a[0]), "r"(a[1]), "r"(a[2]), "r"(a[3]), "r"(b[0]), "r"(b[1]));
}

__device__ __forceinline__ uint32_t pack_h2(__half lo, __half hi) {
    return (uint32_t)__half_as_ushort(lo) | ((uint32_t)__half_as_ushort(hi) << 16);
}

__device__ __forceinline__ float tanh_fast(float x) {
    float y; asm("tanh.approx.f32 %0, %1;" : "=f"(y) : "f"(x)); return y;
}
__device__ __forceinline__ float sigmoid_fast(float x) {
    return fmaf(tanh_fast(0.5f * x), 0.5f, 0.5f);
}

__device__ __forceinline__ void cp16(uint32_t saddr, const void* g) {
    asm volatile("cp.async.cg.shared.global [%0], [%1], 16;" :: "r"(saddr), "l"(g));
}
#define CP_COMMIT() asm volatile("cp.async.commit_group;" ::: "memory")
#define CP_WAIT0()  asm volatile("cp.async.wait_group 0;" ::: "memory")

// ---------------------------------------------------------------------------
// K0: zero accumulator + counts
// ---------------------------------------------------------------------------
__global__ void zero_kernel(float* __restrict__ out) {
    int idx = blockIdx.x * blockDim.x + threadIdx.x;
    int stride = gridDim.x * blockDim.x;
    const int nv4 = N_NODES * D / 4;
    float4 z = make_float4(0.f, 0.f, 0.f, 0.f);
    for (int i = idx; i < nv4; i += stride)
        reinterpret_cast<float4*>(out)[i] = z;
    for (int i = idx; i < N_NODES; i += stride)
        g_counts[i] = 0.f;
}

// ---------------------------------------------------------------------------
// K1: node_hidden = nf @ W_node + b_node  (fp32, exact)
// ---------------------------------------------------------------------------
__global__ __launch_bounds__(256, 2)
void node_gemm_kernel(const float* __restrict__ nf,
                      const float* __restrict__ W,
                      const float* __restrict__ b) {
    extern __shared__ float sm[];
    float* sW = sm;
    float* sX = sm + 128 * PAD;
    const int t = threadIdx.x, tx = t & 31, ty = t >> 5;

    for (int i = t; i < 128 * 32; i += 256) {
        int r = i >> 5, q = i & 31;
        *reinterpret_cast<float4*>(&sW[r * PAD + q * 4]) =
            *reinterpret_cast<const float4*>(&W[r * D + q * 4]);
    }
    float4 bb = *reinterpret_cast<const float4*>(&b[tx * 4]);

    const int ntiles = (N_NODES + NT - 1) / NT;
    for (int tile = blockIdx.x; tile < ntiles; tile += gridDim.x) {
        __syncthreads();
        const int row0 = tile * NT;
        for (int i = t; i < NT * 32; i += 256) {
            int r = i >> 5, q = i & 31;
            int row = row0 + r;
            float4 v = make_float4(0.f, 0.f, 0.f, 0.f);
            if (row < N_NODES)
                v = *reinterpret_cast<const float4*>(&nf[row * D + q * 4]);
            *reinterpret_cast<float4*>(&sX[r * PAD + q * 4]) = v;
        }
        __syncthreads();

        float acc[8][4];
        #pragma unroll
        for (int i = 0; i < 8; i++)
            #pragma unroll
            for (int c = 0; c < 4; c++) acc[i][c] = 0.f;

        #pragma unroll 4
        for (int k4 = 0; k4 < 32; k4++) {
            float ev[8][4];
            #pragma unroll
            for (int i = 0; i < 8; i++) {
                float4 v = *reinterpret_cast<float4*>(&sX[(ty * 8 + i) * PAD + k4 * 4]);
                ev[i][0] = v.x; ev[i][1] = v.y; ev[i][2] = v.z; ev[i][3] = v.w;
            }
            #pragma unroll
            for (int kk = 0; kk < 4; kk++) {
                float4 w = *reinterpret_cast<float4*>(&sW[(k4 * 4 + kk) * PAD + tx * 4]);
                #pragma unroll
                for (int i = 0; i < 8; i++) {
                    float e = ev[i][kk];
                    acc[i][0] += e * w.x; acc[i][1] += e * w.y;
                    acc[i][2] += e * w.z; acc[i][3] += e * w.w;
                }
            }
        }
        #pragma unroll
        for (int i = 0; i < 8; i++) {
            int row = row0 + ty * 8 + i;
            if (row < N_NODES) {
                float4 o;
                o.x = acc[i][0] + bb.x; o.y = acc[i][1] + bb.y;
                o.z = acc[i][2] + bb.z; o.w = acc[i][3] + bb.w;
                *reinterpret_cast<float4*>(&g_hidden[row * D + tx * 4]) = o;
            }
        }
    }
}

// ---------------------------------------------------------------------------
// K2: edge kernel — fp16 mma.sync, double-buffered A, cp.async stage,
//     convert repositioned between mma and epilogue.
//
// 512 threads, 16 warps: grid 4(M) x 4(N), warp tile 32x32.
// SMEM layout (bytes):
//   [0]      sSrc[128]  [512] sDst[128]  [1024] sBg[128]  [1536] sBf[128]
//   [2048]   A fp16 x2 buffers [128][136]      (2 x 34816)
//   [71680]  Wg^T [n=128][k=136] fp16          (34816)
//   [106496] Wf^T                               (34816)
//   [141312] stage fp32 [128][SPITCH=544B]     (69632)
// total 210944.  1 CTA/SM.
//
// Per tile i (A[cur] holds tile i, converted last iteration):
//   issue cp.async stage <- raw(i+1); idx/counts for tile i
//   mma A[cur]
//   CP_WAIT0; sync                      (stage landed long ago)
//   convert stage -> A[nxt]             (overlaps epilogue issue window)
//   epilogue (acc -> red.global)
//   sync; swap buffers
// ---------------------------------------------------------------------------
#define EK_SMEM 210944
#define OFF_A   2048
#define OFF_W   71680
#define OFF_S   141312

__global__ __launch_bounds__(512, 1)
void edge_kernel(const float* __restrict__ ef,
                 const float* __restrict__ Wg, const float* __restrict__ bgp,
                 const float* __restrict__ Wf, const float* __restrict__ bfp,
                 const int*   __restrict__ eidx,
                 float* __restrict__ out) {
    extern __shared__ __align__(16) char smem[];
    int*   sSrc = reinterpret_cast<int*>(smem);
    int*   sDst = reinterpret_cast<int*>(smem + 512);
    float* sBg  = reinterpret_cast<float*>(smem + 1024);
    float* sBf  = reinterpret_cast<float*>(smem + 1536);
    char*  sA   = smem + OFF_A;          // two WBUF buffers
    char*  sW   = smem + OFF_W;
    char*  sS   = smem + OFF_S;

    const int t = threadIdx.x, w = t >> 5, lane = t & 31;
    const int wm = w & 3, wn = w >> 2;

    const uint32_t sbA = smem_u32(sA);
    const uint32_t sbW = smem_u32(sW);
    const uint32_t sbS = smem_u32(sS);

    const int ntiles = N_EDGES / 128;  // 6250 exact
    const int tile0 = blockIdx.x;

    // Prefetch tile0 raw fp32 into stage
    {
        const int e0 = tile0 * 128;
        #pragma unroll
        for (int i = 0; i < 8; i++) {
            int idx = t + i * 512;
            int row = idx >> 5, c16 = idx & 31;
            cp16(sbS + (uint32_t)(row * SPITCH + c16 * 16),
                 &ef[(size_t)(e0 + row) * 128 + c16 * 4]);
        }
        CP_COMMIT();
    }

    if (t < 128) { sBg[t] = bgp[t]; sBf[t] = bfp[t]; }

    // One-time: load + transpose W matrices into resident SMEM as fp16
    for (int m = 0; m < 2; m++) {
        const float* W = m ? Wf : Wg;
        char* buf = sW + m * WBUF;
        for (int idx = t; idx < 16384; idx += 512) {
            int k = idx >> 7, n = idx & 127;
            *reinterpret_cast<__half*>(buf + n * AB + k * 2) = __float2half_rn(W[idx]);
        }
    }
    CP_WAIT0();
    __syncthreads();

    // Convert tile0 into A buffer 0
    #pragma unroll
    for (int i = 0; i < 8; i++) {
        int idx = t + i * 512;
        int row = idx >> 5, c16 = idx & 31;
        float4 v = *reinterpret_cast<const float4*>(sS + row * SPITCH + c16 * 16);
        *reinterpret_cast<uint2*>(sA + row * AB + c16 * 8) = make_uint2(
            pack_h2(__float2half_rn(v.x), __float2half_rn(v.y)),
            pack_h2(__float2half_rn(v.z), __float2half_rn(v.w)));
    }
    __syncthreads();

    // ldmatrix lane addressing (canonical patterns)
    const int ra = lane & 15;
    const int ka = (lane >> 4) * 16;
    const int rb = (lane & 7) + ((lane >> 4) & 1) * 8;
    const int kb = ((lane >> 3) & 1) * 16;

    const uint32_t aoff0 = sbA + (uint32_t)((wm * 32 + ra) * AB + ka);
    const uint32_t boff  = sbW + (uint32_t)((wn * 32 + rb) * AB + kb);

    int cur = 0;
    for (int tile = tile0; tile < ntiles; tile += gridDim.x) {
        const int e0 = tile * 128;

        // Issue prefetch of tile+grid into stage (stage was consumed last iter)
        {
            int tn = tile + gridDim.x;
            if (tn >= ntiles) tn = tile;   // harmless re-fetch on last iter
            const int en = tn * 128;
            #pragma unroll
            for (int i = 0; i < 8; i++) {
                int idx = t + i * 512;
                int row = idx >> 5, c16 = idx & 31;
                cp16(sbS + (uint32_t)(row * SPITCH + c16 * 16),
                     &ef[(size_t)(en + row) * 128 + c16 * 4]);
            }
            CP_COMMIT();
        }

        if (t < 128) {
            int2 p = *reinterpret_cast<const int2*>(&eidx[(size_t)(e0 + t) * 2]);
            sSrc[t] = p.x; sDst[t] = p.y;
            atomicAdd(&g_counts[p.x], 1.0f);
        }

        // mma on A[cur]
        const uint32_t aoff = aoff0 + (uint32_t)(cur * WBUF);
        float acc[2][2][4][4];
        #pragma unroll
        for (int m = 0; m < 2; m++)
            #pragma unroll
            for (int mt = 0; mt < 2; mt++)
                #pragma unroll
                for (int nt = 0; nt < 4; nt++)
                    #pragma unroll
                    for (int i = 0; i < 4; i++) acc[m][mt][nt][i] = 0.f;

        #pragma unroll
        for (int ks = 0; ks < 8; ks++) {
            uint32_t ah[2][4];
            ldsm_x4(ah[0], aoff + ks * 32);
            ldsm_x4(ah[1], aoff + 16 * AB + ks * 32);
            #pragma unroll
            for (int m = 0; m < 2; m++) {
                uint32_t buf = boff + (uint32_t)(m * WBUF);
                uint32_t bh[8];
                ldsm_x4(&bh[0], buf + ks * 32);
                ldsm_x4(&bh[4], buf + (uint32_t)(16 * AB) + ks * 32);
                #pragma unroll
                for (int mt = 0; mt < 2; mt++)
                    #pragma unroll
                    for (int nt = 0; nt < 4; nt++)
                        mma_fp16(acc[m][mt][nt], ah[mt], &bh[nt * 2]);
            }
        }

        CP_WAIT0();        // stage (tile+grid) landed — issued a full mma ago
        __syncthreads();   // stage visible to all; idx stable for epilogue

        // Convert stage -> A[nxt]; independent of acc, overlaps epilogue below
        {
            char* An = sA + (cur ^ 1) * WBUF;
            #pragma unroll
            for (int i = 0; i < 8; i++) {
                int idx = t + i * 512;
                int row = idx >> 5, c16 = idx & 31;
                float4 v = *reinterpret_cast<const float4*>(sS + row * SPITCH + c16 * 16);
                *reinterpret_cast<uint2*>(An + row * AB + c16 * 8) = make_uint2(
                    pack_h2(__float2half_rn(v.x), __float2half_rn(v.y)),
                    pack_h2(__float2half_rn(v.z), __float2half_rn(v.w)));
            }
        }

        // Epilogue: rows wm*32 + mt*16 + (lane>>2) + rr*8,
        //           cols wn*32 + nt*8 + (lane&3)*2
        #pragma unroll
        for (int mt = 0; mt < 2; mt++) {
            #pragma unroll
            for (int rr = 0; rr < 2; rr++) {
                const int row = wm * 32 + mt * 16 + (lane >> 2) + rr * 8;
                const int dst = sDst[row], src = sSrc[row];
                const float* hp = &g_hidden[(size_t)dst * 128];
                float* op = &out[(size_t)src * 128];
                #pragma unroll
                for (int nt = 0; nt < 4; nt++) {
                    const int c = wn * 32 + nt * 8 + (lane & 3) * 2;
                    float2 nb = *reinterpret_cast<const float2*>(hp + c);
                    float g0 = sigmoid_fast(acc[0][mt][nt][rr * 2 + 0] + sBg[c]);
                    float g1 = sigmoid_fast(acc[0][mt][nt][rr * 2 + 1] + sBg[c + 1]);
                    float m0 = g0 * (acc[1][mt][nt][rr * 2 + 0] + sBf[c])     * nb.x;
                    float m1 = g1 * (acc[1][mt][nt][rr * 2 + 1] + sBf[c + 1]) * nb.y;
                    red_add_v2(op + c, m0, m1);
                }
            }
        }

        __syncthreads();   // converts done (A[nxt] ready), stage consumed, idx free
        cur ^= 1;
    }
}

// ---------------------------------------------------------------------------
// K3: finalize — out = relu(bn(hidden + sums/max(counts,1)))
// ---------------------------------------------------------------------------
__global__ void finalize_kernel(const float* __restrict__ gamma,
                                const float* __restrict__ beta,
                                const float* __restrict__ mean,
                                const float* __restrict__ var,
                                float* __restrict__ out) {
    int idx = blockIdx.x * blockDim.x + threadIdx.x;
    const int total = N_NODES * 32;
    if (idx >= total) return;
    int node = idx >> 5;
    int q    = idx & 31;
    float inv = 1.f / fmaxf(g_counts[node], 1.f);

    float4 s  = reinterpret_cast<float4*>(out)[idx];
    float4 h  = *reinterpret_cast<const float4*>(&g_hidden[node * D + q * 4]);
    float4 mu = *reinterpret_cast<const float4*>(&mean[q * 4]);
    float4 vr = *reinterpret_cast<const float4*>(&var[q * 4]);
    float4 ga = *reinterpret_cast<const float4*>(&gamma[q * 4]);
    float4 be = *reinterpret_cast<const float4*>(&beta[q * 4]);

    float4 o;
    o.x = fmaxf((h.x + s.x * inv - mu.x) * rsqrtf(vr.x + BN_EPS) * ga.x + be.x, 0.f);
    o.y = fmaxf((h.y + s.y * inv - mu.y) * rsqrtf(vr.y + BN_EPS) * ga.y + be.y, 0.f);
    o.z = fmaxf((h.z + s.z * inv - mu.z) * rsqrtf(vr.z + BN_EPS) * ga.z + be.z, 0.f);
    o.w = fmaxf((h.w + s.w * inv - mu.w) * rsqrtf(vr.w + BN_EPS) * ga.w + be.w, 0.f);
    reinterpret_cast<float4*>(out)[idx] = o;
}

// ---------------------------------------------------------------------------
// launch
// ---------------------------------------------------------------------------
extern "C" void kernel_launch(void* const* d_in, const int* in_sizes, int n_in,
                              void* d_out, int out_size) {
    const float* nf    = (const float*)d_in[0];
    const float* ef    = (const float*)d_in[1];
    const float* Wn    = (const float*)d_in[2];
    const float* bn_   = (const float*)d_in[3];
    const float* Wg    = (const float*)d_in[4];
    const float* bg    = (const float*)d_in[5];
    const float* Wf    = (const float*)d_in[6];
    const float* bf    = (const float*)d_in[7];
    const float* gamma = (const float*)d_in[8];
    const float* beta  = (const float*)d_in[9];
    const float* mean  = (const float*)d_in[10];
    const float* var   = (const float*)d_in[11];
    const int*   eidx  = (const int*)d_in[12];
    float* out = (float*)d_out;

    const int node_smem = (128 * PAD + NT * PAD) * (int)sizeof(float);

    int dev = 0, nsm = 148;
    cudaGetDevice(&dev);
    cudaDeviceGetAttribute(&nsm, cudaDevAttrMultiProcessorCount, dev);
    cudaFuncSetAttribute(node_gemm_kernel, cudaFuncAttributeMaxDynamicSharedMemorySize, node_smem);
    cudaFuncSetAttribute(edge_kernel,      cudaFuncAttributeMaxDynamicSharedMemorySize, EK_SMEM);

    zero_kernel<<<512, 256>>>(out);
    node_gemm_kernel<<<2 * nsm, 256, node_smem>>>(nf, Wn, bn_);
    edge_kernel<<<nsm, 512, EK_SMEM>>>(ef, Wg, bg, Wf, bf, eidx, out);
    finalize_kernel<<<(N_NODES * 32 + 255) / 256, 256>>>(gamma, beta, mean, var, out);
}

// round 10
// speedup vs baseline: 3.4444x; 1.0198x over previous
#include <cuda_runtime.h>
#include <cuda_fp16.h>
#include <cstdint>

#define N_NODES 50000
#define N_EDGES 800000
#define D 128
#define BN_EPS 1e-3f

#define NT 64          // nodes per tile (node gemm)
#define PAD 132        // node gemm smem padding

#define AB 272         // bytes per fp16 smem row (136 fp16, pitch)
#define WBUF 34816     // bytes per 128x136 fp16 buffer
#define SPITCH 544     // stage fp32 row pitch bytes (512 data + 32 pad)

// Scratch
__device__ float g_hidden[N_NODES * D];
__device__ float g_counts[N_NODES];

// ---------------------------------------------------------------------------
// helpers
// ---------------------------------------------------------------------------
__device__ __forceinline__ uint32_t smem_u32(const void* p) {
    uint32_t a;
    asm("{ .reg .u64 t; cvta.to.shared.u64 t, %1; cvt.u32.u64 %0, t; }" : "=r"(a) : "l"(p));
    return a;
}

__device__ __forceinline__ void red_add_v4(float* addr, float a, float b, float c, float d) {
    asm volatile("red.global.add.v4.f32 [%0], {%1, %2, %3, %4};"
                 :: "l"(addr), "f"(a), "f"(b), "f"(c), "f"(d) : "memory");
}

__device__ __forceinline__ void ldsm_x4(uint32_t* r, uint32_t addr) {
    asm volatile("ldmatrix.sync.aligned.m8n8.x4.shared.b16 {%0,%1,%2,%3}, [%4];"
                 : "=r"(r[0]), "=r"(r[1]), "=r"(r[2]), "=r"(r[3]) : "r"(addr));
}

__device__ __forceinline__ void mma_fp16(float* c, const uint32_t* a, const uint32_t* b) {
    asm volatile("mma.sync.aligned.m16n8k16.row.col.f32.f16.f16.f32 "
                 "{%0,%1,%2,%3}, {%4,%5,%6,%7}, {%8,%9}, {%0,%1,%2,%3};"
                 : "+f"(c[0]), "+f"(c[1]), "+f"(c[2]), "+f"(c[3])
                 : "r"(a[0]), "r"(a[1]), "r"(a[2]), "r"(a[3]), "r"(b[0]), "r"(b[1]));
}

__device__ __forceinline__ uint32_t pack_h2(__half lo, __half hi) {
    return (uint32_t)__half_as_ushort(lo) | ((uint32_t)__half_as_ushort(hi) << 16);
}

__device__ __forceinline__ float tanh_fast(float x) {
    float y; asm("tanh.approx.f32 %0, %1;" : "=f"(y) : "f"(x)); return y;
}
__device__ __forceinline__ float sigmoid_fast(float x) {
    return fmaf(tanh_fast(0.5f * x), 0.5f, 0.5f);
}

__device__ __forceinline__ void cp16(uint32_t saddr, const void* g) {
    asm volatile("cp.async.cg.shared.global [%0], [%1], 16;" :: "r"(saddr), "l"(g));
}
#define CP_COMMIT() asm volatile("cp.async.commit_group;" ::: "memory")
#define CP_WAIT0()  asm volatile("cp.async.wait_group 0;" ::: "memory")

// ---------------------------------------------------------------------------
// K0: zero accumulator + counts
// ---------------------------------------------------------------------------
__global__ void zero_kernel(float* __restrict__ out) {
    int idx = blockIdx.x * blockDim.x + threadIdx.x;
    int stride = gridDim.x * blockDim.x;
    const int nv4 = N_NODES * D / 4;
    float4 z = make_float4(0.f, 0.f, 0.f, 0.f);
    for (int i = idx; i < nv4; i += stride)
        reinterpret_cast<float4*>(out)[i] = z;
    for (int i = idx; i < N_NODES; i += stride)
        g_counts[i] = 0.f;
}

// ---------------------------------------------------------------------------
// K1: node_hidden = nf @ W_node + b_node  (fp32, exact)
// ---------------------------------------------------------------------------
__global__ __launch_bounds__(256, 2)
void node_gemm_kernel(const float* __restrict__ nf,
                      const float* __restrict__ W,
                      const float* __restrict__ b) {
    extern __shared__ float sm[];
    float* sW = sm;
    float* sX = sm + 128 * PAD;
    const int t = threadIdx.x, tx = t & 31, ty = t >> 5;

    for (int i = t; i < 128 * 32; i += 256) {
        int r = i >> 5, q = i & 31;
        *reinterpret_cast<float4*>(&sW[r * PAD + q * 4]) =
            *reinterpret_cast<const float4*>(&W[r * D + q * 4]);
    }
    float4 bb = *reinterpret_cast<const float4*>(&b[tx * 4]);

    const int ntiles = (N_NODES + NT - 1) / NT;
    for (int tile = blockIdx.x; tile < ntiles; tile += gridDim.x) {
        __syncthreads();
        const int row0 = tile * NT;
        for (int i = t; i < NT * 32; i += 256) {
            int r = i >> 5, q = i & 31;
            int row = row0 + r;
            float4 v = make_float4(0.f, 0.f, 0.f, 0.f);
            if (row < N_NODES)
                v = *reinterpret_cast<const float4*>(&nf[row * D + q * 4]);
            *reinterpret_cast<float4*>(&sX[r * PAD + q * 4]) = v;
        }
        __syncthreads();

        float acc[8][4];
        #pragma unroll
        for (int i = 0; i < 8; i++)
            #pragma unroll
            for (int c = 0; c < 4; c++) acc[i][c] = 0.f;

        #pragma unroll 4
        for (int k4 = 0; k4 < 32; k4++) {
            float ev[8][4];
            #pragma unroll
            for (int i = 0; i < 8; i++) {
                float4 v = *reinterpret_cast<float4*>(&sX[(ty * 8 + i) * PAD + k4 * 4]);
                ev[i][0] = v.x; ev[i][1] = v.y; ev[i][2] = v.z; ev[i][3] = v.w;
            }
            #pragma unroll
            for (int kk = 0; kk < 4; kk++) {
                float4 w = *reinterpret_cast<float4*>(&sW[(k4 * 4 + kk) * PAD + tx * 4]);
                #pragma unroll
                for (int i = 0; i < 8; i++) {
                    float e = ev[i][kk];
                    acc[i][0] += e * w.x; acc[i][1] += e * w.y;
                    acc[i][2] += e * w.z; acc[i][3] += e * w.w;
                }
            }
        }
        #pragma unroll
        for (int i = 0; i < 8; i++) {
            int row = row0 + ty * 8 + i;
            if (row < N_NODES) {
                float4 o;
                o.x = acc[i][0] + bb.x; o.y = acc[i][1] + bb.y;
                o.z = acc[i][2] + bb.z; o.w = acc[i][3] + bb.w;
                *reinterpret_cast<float4*>(&g_hidden[row * D + tx * 4]) = o;
            }
        }
    }
}

// ---------------------------------------------------------------------------
// K2: edge kernel — fp16 mma.sync, double-buffered A, cp.async stage,
//     pair-exchange epilogue with red.v4, barrier-free epilogue/mma overlap.
//
// 512 threads, 16 warps: grid 4(M) x 4(N), warp tile 32x32.
// SMEM (bytes):
//   [1024] sBg[128]  [1536] sBf[128]
//   [2048]   A fp16 x2 buffers [128][136]      (2 x 34816)
//   [71680]  Wg^T [n=128][k=136] fp16          (34816)
//   [106496] Wf^T                               (34816)
//   [141312] stage fp32 [128][SPITCH=544B]     (69632)
// total 210944.  1 CTA/SM.
//
// Per tile i (invariant at loop top: A[cur]=tile i published; stage holds
// raw(i+grid) in flight):
//   idx regs (direct LDG) + counts; mma A[cur]
//   CP_WAIT0; sync                     (stage landed)
//   convert stage -> A[nxt]; sync      (publish A[nxt]; stage consumed)
//   cp.async stage <- raw(i+2*grid)
//   epilogue: shfl pair-exchange -> even lane = row r cols[0:4),
//             odd = row r+8; gather LDG.128; red.v4   (NO barrier after —
//             overlaps next iteration's mma in the same epoch)
// ---------------------------------------------------------------------------
#define EK_SMEM 210944
#define OFF_A   2048
#define OFF_W   71680
#define OFF_S   141312

__global__ __launch_bounds__(512, 1)
void edge_kernel(const float* __restrict__ ef,
                 const float* __restrict__ Wg, const float* __restrict__ bgp,
                 const float* __restrict__ Wf, const float* __restrict__ bfp,
                 const int*   __restrict__ eidx,
                 float* __restrict__ out) {
    extern __shared__ __align__(16) char smem[];
    float* sBg  = reinterpret_cast<float*>(smem + 1024);
    float* sBf  = reinterpret_cast<float*>(smem + 1536);
    char*  sA   = smem + OFF_A;          // two WBUF buffers
    char*  sW   = smem + OFF_W;
    char*  sS   = smem + OFF_S;

    const int t = threadIdx.x, w = t >> 5, lane = t & 31;
    const int wm = w & 3, wn = w >> 2;
    const int pl = lane & 1;             // pair role: 0 -> row r, 1 -> row r+8
    const int cb = (lane & 2) * 2;       // 4-col group base within n8 tile

    const uint32_t sbA = smem_u32(sA);
    const uint32_t sbW = smem_u32(sW);
    const uint32_t sbS = smem_u32(sS);

    const int ntiles = N_EDGES / 128;  // 6250 exact
    const int tile0 = blockIdx.x;

    // Prefetch tile0 raw fp32 into stage
    {
        const int e0 = tile0 * 128;
        #pragma unroll
        for (int i = 0; i < 8; i++) {
            int idx = t + i * 512;
            int row = idx >> 5, c16 = idx & 31;
            cp16(sbS + (uint32_t)(row * SPITCH + c16 * 16),
                 &ef[(size_t)(e0 + row) * 128 + c16 * 4]);
        }
        CP_COMMIT();
    }

    if (t < 128) { sBg[t] = bgp[t]; sBf[t] = bfp[t]; }

    // One-time: load + transpose W matrices into resident SMEM as fp16
    for (int m = 0; m < 2; m++) {
        const float* W = m ? Wf : Wg;
        char* buf = sW + m * WBUF;
        for (int idx = t; idx < 16384; idx += 512) {
            int k = idx >> 7, n = idx & 127;
            *reinterpret_cast<__half*>(buf + n * AB + k * 2) = __float2half_rn(W[idx]);
        }
    }
    CP_WAIT0();
    __syncthreads();

    // Convert tile0 into A buffer 0
    #pragma unroll
    for (int i = 0; i < 8; i++) {
        int idx = t + i * 512;
        int row = idx >> 5, c16 = idx & 31;
        float4 v = *reinterpret_cast<const float4*>(sS + row * SPITCH + c16 * 16);
        *reinterpret_cast<uint2*>(sA + row * AB + c16 * 8) = make_uint2(
            pack_h2(__float2half_rn(v.x), __float2half_rn(v.y)),
            pack_h2(__float2half_rn(v.z), __float2half_rn(v.w)));
    }
    __syncthreads();   // A[0] published; stage consumed

    // Prefetch tile0+grid into stage (in flight across first iteration's mma)
    {
        int tn = tile0 + gridDim.x;
        if (tn >= ntiles) tn = tile0;
        const int en = tn * 128;
        #pragma unroll
        for (int i = 0; i < 8; i++) {
            int idx = t + i * 512;
            int row = idx >> 5, c16 = idx & 31;
            cp16(sbS + (uint32_t)(row * SPITCH + c16 * 16),
                 &ef[(size_t)(en + row) * 128 + c16 * 4]);
        }
        CP_COMMIT();
    }

    // ldmatrix lane addressing (canonical patterns)
    const int ra = lane & 15;
    const int ka = (lane >> 4) * 16;
    const int rb = (lane & 7) + ((lane >> 4) & 1) * 8;
    const int kb = ((lane >> 3) & 1) * 16;

    const uint32_t aoff0 = sbA + (uint32_t)((wm * 32 + ra) * AB + ka);
    const uint32_t boff  = sbW + (uint32_t)((wn * 32 + rb) * AB + kb);

    int cur = 0;
    for (int tile = tile0; tile < ntiles; tile += gridDim.x) {
        const int e0 = tile * 128;

        // Per-thread edge indices for the 2 rows this thread reduces (LDG,
        // latency hidden under mma below). Row: wm*32+mt*16+(lane>>2)+pl*8.
        int srcR[2], dstR[2];
        #pragma unroll
        for (int mt = 0; mt < 2; mt++) {
            int r = wm * 32 + mt * 16 + (lane >> 2) + pl * 8;
            int2 p = *reinterpret_cast<const int2*>(&eidx[(size_t)(e0 + r) * 2]);
            srcR[mt] = p.x; dstR[mt] = p.y;
        }
        if (t < 128)
            atomicAdd(&g_counts[eidx[(size_t)(e0 + t) * 2]], 1.0f);

        // mma on A[cur]
        const uint32_t aoff = aoff0 + (uint32_t)(cur * WBUF);
        float acc[2][2][4][4];
        #pragma unroll
        for (int m = 0; m < 2; m++)
            #pragma unroll
            for (int mt = 0; mt < 2; mt++)
                #pragma unroll
                for (int nt = 0; nt < 4; nt++)
                    #pragma unroll
                    for (int i = 0; i < 4; i++) acc[m][mt][nt][i] = 0.f;

        #pragma unroll
        for (int ks = 0; ks < 8; ks++) {
            uint32_t ah[2][4];
            ldsm_x4(ah[0], aoff + ks * 32);
            ldsm_x4(ah[1], aoff + 16 * AB + ks * 32);
            #pragma unroll
            for (int m = 0; m < 2; m++) {
                uint32_t buf = boff + (uint32_t)(m * WBUF);
                uint32_t bh[8];
                ldsm_x4(&bh[0], buf + ks * 32);
                ldsm_x4(&bh[4], buf + (uint32_t)(16 * AB) + ks * 32);
                #pragma unroll
                for (int mt = 0; mt < 2; mt++)
                    #pragma unroll
                    for (int nt = 0; nt < 4; nt++)
                        mma_fp16(acc[m][mt][nt], ah[mt], &bh[nt * 2]);
            }
        }

        CP_WAIT0();        // stage (tile+grid) landed
        __syncthreads();   // all mma reads of A[cur] done; stage visible

        // Convert stage -> A[nxt]
        {
            char* An = sA + (cur ^ 1) * WBUF;
            #pragma unroll
            for (int i = 0; i < 8; i++) {
                int idx = t + i * 512;
                int row = idx >> 5, c16 = idx & 31;
                float4 v = *reinterpret_cast<const float4*>(sS + row * SPITCH + c16 * 16);
                *reinterpret_cast<uint2*>(An + row * AB + c16 * 8) = make_uint2(
                    pack_h2(__float2half_rn(v.x), __float2half_rn(v.y)),
                    pack_h2(__float2half_rn(v.z), __float2half_rn(v.w)));
            }
        }
        __syncthreads();   // A[nxt] published; stage consumed by everyone

        // Issue prefetch for tile+2*grid (stage free; lands during epilogue+next mma)
        {
            int tn = tile + 2 * gridDim.x;
            if (tn >= ntiles) tn = tile;
            const int en = tn * 128;
            #pragma unroll
            for (int i = 0; i < 8; i++) {
                int idx = t + i * 512;
                int row = idx >> 5, c16 = idx & 31;
                cp16(sbS + (uint32_t)(row * SPITCH + c16 * 16),
                     &ef[(size_t)(en + row) * 128 + c16 * 4]);
            }
            CP_COMMIT();
        }

        // Epilogue (no trailing barrier — overlaps next iteration's mma).
        // Pair-exchange: even lane handles row r cols [C,C+4), odd row r+8.
        #pragma unroll
        for (int mt = 0; mt < 2; mt++) {
            const float* hp = &g_hidden[(size_t)dstR[mt] * 128];
            float* op = &out[(size_t)srcR[mt] * 128];
            #pragma unroll
            for (int nt = 0; nt < 4; nt++) {
                const int C = wn * 32 + nt * 8 + cb;
                // send partner's-role values, keep own-role values
                float sg0 = pl ? acc[0][mt][nt][0] : acc[0][mt][nt][2];
                float sg1 = pl ? acc[0][mt][nt][1] : acc[0][mt][nt][3];
                float sf0 = pl ? acc[1][mt][nt][0] : acc[1][mt][nt][2];
                float sf1 = pl ? acc[1][mt][nt][1] : acc[1][mt][nt][3];
                float kg0 = pl ? acc[0][mt][nt][2] : acc[0][mt][nt][0];
                float kg1 = pl ? acc[0][mt][nt][3] : acc[0][mt][nt][1];
                float kf0 = pl ? acc[1][mt][nt][2] : acc[1][mt][nt][0];
                float kf1 = pl ? acc[1][mt][nt][3] : acc[1][mt][nt][1];
                float rg0 = __shfl_xor_sync(0xffffffffu, sg0, 1);
                float rg1 = __shfl_xor_sync(0xffffffffu, sg1, 1);
                float rf0 = __shfl_xor_sync(0xffffffffu, sf0, 1);
                float rf1 = __shfl_xor_sync(0xffffffffu, sf1, 1);
                // assemble cols C..C+3 (even: keep|recv ; odd: recv|keep)
                float gA0 = pl ? rg0 : kg0;
                float gA1 = pl ? rg1 : kg1;
                float gA2 = pl ? kg0 : rg0;
                float gA3 = pl ? kg1 : rg1;
                float fA0 = pl ? rf0 : kf0;
                float fA1 = pl ? rf1 : kf1;
                float fA2 = pl ? kf0 : rf0;
                float fA3 = pl ? kf1 : rf1;

                float4 nb  = *reinterpret_cast<const float4*>(hp + C);
                float4 bg4 = *reinterpret_cast<const float4*>(sBg + C);
                float4 bf4 = *reinterpret_cast<const float4*>(sBf + C);
                float g0 = sigmoid_fast(gA0 + bg4.x);
                float g1 = sigmoid_fast(gA1 + bg4.y);
                float g2 = sigmoid_fast(gA2 + bg4.z);
                float g3 = sigmoid_fast(gA3 + bg4.w);
                float m0 = g0 * (fA0 + bf4.x) * nb.x;
                float m1 = g1 * (fA1 + bf4.y) * nb.y;
                float m2 = g2 * (fA2 + bf4.z) * nb.z;
                float m3 = g3 * (fA3 + bf4.w) * nb.w;
                red_add_v4(op + C, m0, m1, m2, m3);
            }
        }

        cur ^= 1;
    }
}

// ---------------------------------------------------------------------------
// K3: finalize — out = relu(bn(hidden + sums/max(counts,1)))
// ---------------------------------------------------------------------------
__global__ void finalize_kernel(const float* __restrict__ gamma,
                                const float* __restrict__ beta,
                                const float* __restrict__ mean,
                                const float* __restrict__ var,
                                float* __restrict__ out) {
    int idx = blockIdx.x * blockDim.x + threadIdx.x;
    const int total = N_NODES * 32;
    if (idx >= total) return;
    int node = idx >> 5;
    int q    = idx & 31;
    float inv = 1.f / fmaxf(g_counts[node], 1.f);

    float4 s  = reinterpret_cast<float4*>(out)[idx];
    float4 h  = *reinterpret_cast<const float4*>(&g_hidden[node * D + q * 4]);
    float4 mu = *reinterpret_cast<const float4*>(&mean[q * 4]);
    float4 vr = *reinterpret_cast<const float4*>(&var[q * 4]);
    float4 ga = *reinterpret_cast<const float4*>(&gamma[q * 4]);
    float4 be = *reinterpret_cast<const float4*>(&beta[q * 4]);

    float4 o;
    o.x = fmaxf((h.x + s.x * inv - mu.x) * rsqrtf(vr.x + BN_EPS) * ga.x + be.x, 0.f);
    o.y = fmaxf((h.y + s.y * inv - mu.y) * rsqrtf(vr.y + BN_EPS) * ga.y + be.y, 0.f);
    o.z = fmaxf((h.z + s.z * inv - mu.z) * rsqrtf(vr.z + BN_EPS) * ga.z + be.z, 0.f);
    o.w = fmaxf((h.w + s.w * inv - mu.w) * rsqrtf(vr.w + BN_EPS) * ga.w + be.w, 0.f);
    reinterpret_cast<float4*>(out)[idx] = o;
}

// ---------------------------------------------------------------------------
// launch
// ---------------------------------------------------------------------------
extern "C" void kernel_launch(void* const* d_in, const int* in_sizes, int n_in,
                              void* d_out, int out_size) {
    const float* nf    = (const float*)d_in[0];
    const float* ef    = (const float*)d_in[1];
    const float* Wn    = (const float*)d_in[2];
    const float* bn_   = (const float*)d_in[3];
    const float* Wg    = (const float*)d_in[4];
    const float* bg    = (const float*)d_in[5];
    const float* Wf    = (const float*)d_in[6];
    const float* bf    = (const float*)d_in[7];
    const float* gamma = (const float*)d_in[8];
    const float* beta  = (const float*)d_in[9];
    const float* mean  = (const float*)d_in[10];
    const float* var   = (const float*)d_in[11];
    const int*   eidx  = (const int*)d_in[12];
    float* out = (float*)d_out;

    const int node_smem = (128 * PAD + NT * PAD) * (int)sizeof(float);

    int dev = 0, nsm = 148;
    cudaGetDevice(&dev);
    cudaDeviceGetAttribute(&nsm, cudaDevAttrMultiProcessorCount, dev);
    cudaFuncSetAttribute(node_gemm_kernel, cudaFuncAttributeMaxDynamicSharedMemorySize, node_smem);
    cudaFuncSetAttribute(edge_kernel,      cudaFuncAttributeMaxDynamicSharedMemorySize, EK_SMEM);

    zero_kernel<<<512, 256>>>(out);
    node_gemm_kernel<<<2 * nsm, 256, node_smem>>>(nf, Wn, bn_);
    edge_kernel<<<nsm, 512, EK_SMEM>>>(ef, Wg, bg, Wf, bf, eidx, out);
    finalize_kernel<<<(N_NODES * 32 + 255) / 256, 256>>>(gamma, beta, mean, var, out);
}

// round 12
// speedup vs baseline: 3.5302x; 1.0249x over previous
#include <cuda_runtime.h>
#include <cuda_fp16.h>
#include <cstdint>

#define N_NODES 50000
#define N_EDGES 800000
#define D 128
#define BN_EPS 1e-3f

#define NT 64          // nodes per tile (node gemm)
#define PAD 132        // node gemm smem padding

#define AB 272         // bytes per fp16 smem row (136 fp16, pitch)
#define WBUF 34816     // bytes per 128x136 fp16 buffer
#define SPITCH 544     // stage fp32 row pitch bytes (512 data + 32 pad)

// Scratch
__device__ float g_hidden[N_NODES * D];
__device__ float g_counts[N_NODES];

// ---------------------------------------------------------------------------
// helpers
// ---------------------------------------------------------------------------
__device__ __forceinline__ uint32_t smem_u32(const void* p) {
    uint32_t a;
    asm("{ .reg .u64 t; cvta.to.shared.u64 t, %1; cvt.u32.u64 %0, t; }" : "=r"(a) : "l"(p));
    return a;
}

__device__ __forceinline__ void red_add_v4(float* addr, float a, float b, float c, float d) {
    asm volatile("red.global.add.v4.f32 [%0], {%1, %2, %3, %4};"
                 :: "l"(addr), "f"(a), "f"(b), "f"(c), "f"(d) : "memory");
}

__device__ __forceinline__ void ldsm_x4(uint32_t* r, uint32_t addr) {
    asm volatile("ldmatrix.sync.aligned.m8n8.x4.shared.b16 {%0,%1,%2,%3}, [%4];"
                 : "=r"(r[0]), "=r"(r[1]), "=r"(r[2]), "=r"(r[3]) : "r"(addr));
}

// fp16-accumulator mma: D fragment = 2 regs (reg0 = row r cols {c,c+1} packed,
// reg1 = row r+8 cols {c,c+1} packed)
__device__ __forceinline__ void mma_fp16acc(uint32_t* c, const uint32_t* a, const uint32_t* b) {
    asm volatile("mma.sync.aligned.m16n8k16.row.col.f16.f16.f16.f16 "
                 "{%0,%1}, {%2,%3,%4,%5}, {%6,%7}, {%0,%1};"
                 : "+r"(c[0]), "+r"(c[1])
                 : "r"(a[0]), "r"(a[1]), "r"(a[2]), "r"(a[3]), "r"(b[0]), "r"(b[1]));
}

__device__ __forceinline__ uint32_t pack_h2(__half lo, __half hi) {
    return (uint32_t)__half_as_ushort(lo) | ((uint32_t)__half_as_ushort(hi) << 16);
}

__device__ __forceinline__ float tanh_fast(float x) {
    float y; asm("tanh.approx.f32 %0, %1;" : "=f"(y) : "f"(x)); return y;
}
__device__ __forceinline__ float sigmoid_fast(float x) {
    return fmaf(tanh_fast(0.5f * x), 0.5f, 0.5f);
}

__device__ __forceinline__ void cp16(uint32_t saddr, const void* g) {
    asm volatile("cp.async.cg.shared.global [%0], [%1], 16;" :: "r"(saddr), "l"(g));
}
#define CP_COMMIT() asm volatile("cp.async.commit_group;" ::: "memory")
#define CP_WAIT0()  asm volatile("cp.async.wait_group 0;" ::: "memory")

// ---------------------------------------------------------------------------
// K0: zero accumulator + counts
// ---------------------------------------------------------------------------
__global__ void zero_kernel(float* __restrict__ out) {
    int idx = blockIdx.x * blockDim.x + threadIdx.x;
    int stride = gridDim.x * blockDim.x;
    const int nv4 = N_NODES * D / 4;
    float4 z = make_float4(0.f, 0.f, 0.f, 0.f);
    for (int i = idx; i < nv4; i += stride)
        reinterpret_cast<float4*>(out)[i] = z;
    for (int i = idx; i < N_NODES; i += stride)
        g_counts[i] = 0.f;
}

// ---------------------------------------------------------------------------
// K1: node_hidden = nf @ W_node + b_node  (fp32, exact)
// ---------------------------------------------------------------------------
__global__ __launch_bounds__(256, 2)
void node_gemm_kernel(const float* __restrict__ nf,
                      const float* __restrict__ W,
                      const float* __restrict__ b) {
    extern __shared__ float sm[];
    float* sW = sm;
    float* sX = sm + 128 * PAD;
    const int t = threadIdx.x, tx = t & 31, ty = t >> 5;

    for (int i = t; i < 128 * 32; i += 256) {
        int r = i >> 5, q = i & 31;
        *reinterpret_cast<float4*>(&sW[r * PAD + q * 4]) =
            *reinterpret_cast<const float4*>(&W[r * D + q * 4]);
    }
    float4 bb = *reinterpret_cast<const float4*>(&b[tx * 4]);

    const int ntiles = (N_NODES + NT - 1) / NT;
    for (int tile = blockIdx.x; tile < ntiles; tile += gridDim.x) {
        __syncthreads();
        const int row0 = tile * NT;
        for (int i = t; i < NT * 32; i += 256) {
            int r = i >> 5, q = i & 31;
            int row = row0 + r;
            float4 v = make_float4(0.f, 0.f, 0.f, 0.f);
            if (row < N_NODES)
                v = *reinterpret_cast<const float4*>(&nf[row * D + q * 4]);
            *reinterpret_cast<float4*>(&sX[r * PAD + q * 4]) = v;
        }
        __syncthreads();

        float acc[8][4];
        #pragma unroll
        for (int i = 0; i < 8; i++)
            #pragma unroll
            for (int c = 0; c < 4; c++) acc[i][c] = 0.f;

        #pragma unroll 4
        for (int k4 = 0; k4 < 32; k4++) {
            float ev[8][4];
            #pragma unroll
            for (int i = 0; i < 8; i++) {
                float4 v = *reinterpret_cast<float4*>(&sX[(ty * 8 + i) * PAD + k4 * 4]);
                ev[i][0] = v.x; ev[i][1] = v.y; ev[i][2] = v.z; ev[i][3] = v.w;
            }
            #pragma unroll
            for (int kk = 0; kk < 4; kk++) {
                float4 w = *reinterpret_cast<float4*>(&sW[(k4 * 4 + kk) * PAD + tx * 4]);
                #pragma unroll
                for (int i = 0; i < 8; i++) {
                    float e = ev[i][kk];
                    acc[i][0] += e * w.x; acc[i][1] += e * w.y;
                    acc[i][2] += e * w.z; acc[i][3] += e * w.w;
                }
            }
        }
        #pragma unroll
        for (int i = 0; i < 8; i++) {
            int row = row0 + ty * 8 + i;
            if (row < N_NODES) {
                float4 o;
                o.x = acc[i][0] + bb.x; o.y = acc[i][1] + bb.y;
                o.z = acc[i][2] + bb.z; o.w = acc[i][3] + bb.w;
                *reinterpret_cast<float4*>(&g_hidden[row * D + tx * 4]) = o;
            }
        }
    }
}

// ---------------------------------------------------------------------------
// K2: edge kernel — fp16 mma.sync with FP16 ACCUMULATORS (testing the
//     half-rate-fp32-acc hypothesis), double-buffered A, cp.async stage,
//     1-shfl pair-exchange epilogue with red.v4.
//
// 512 threads, 16 warps: grid 4(M) x 4(N), warp tile 32x32.
// SMEM (bytes):
//   [1024] sBg[128]  [1536] sBf[128]
//   [2048]   A fp16 x2 buffers [128][136]      (2 x 34816)
//   [71680]  Wg^T [n=128][k=136] fp16          (34816)
//   [106496] Wf^T                               (34816)
//   [141312] stage fp32 [128][SPITCH=544B]     (69632)
// total 210944.  1 CTA/SM.
// ---------------------------------------------------------------------------
#define EK_SMEM 210944
#define OFF_A   2048
#define OFF_W   71680
#define OFF_S   141312

__global__ __launch_bounds__(512, 1)
void edge_kernel(const float* __restrict__ ef,
                 const float* __restrict__ Wg, const float* __restrict__ bgp,
                 const float* __restrict__ Wf, const float* __restrict__ bfp,
                 const int*   __restrict__ eidx,
                 float* __restrict__ out) {
    extern __shared__ __align__(16) char smem[];
    float* sBg  = reinterpret_cast<float*>(smem + 1024);
    float* sBf  = reinterpret_cast<float*>(smem + 1536);
    char*  sA   = smem + OFF_A;          // two WBUF buffers
    char*  sW   = smem + OFF_W;
    char*  sS   = smem + OFF_S;

    const int t = threadIdx.x, w = t >> 5, lane = t & 31;
    const int wm = w & 3, wn = w >> 2;
    const int pl = lane & 1;             // pair role: 0 -> row r, 1 -> row r+8
    const int cb = (lane & 2) * 2;       // 4-col group base within n8 tile

    const uint32_t sbA = smem_u32(sA);
    const uint32_t sbW = smem_u32(sW);
    const uint32_t sbS = smem_u32(sS);

    const int ntiles = N_EDGES / 128;  // 6250 exact
    const int tile0 = blockIdx.x;

    // Prefetch tile0 raw fp32 into stage
    {
        const int e0 = tile0 * 128;
        #pragma unroll
        for (int i = 0; i < 8; i++) {
            int idx = t + i * 512;
            int row = idx >> 5, c16 = idx & 31;
            cp16(sbS + (uint32_t)(row * SPITCH + c16 * 16),
                 &ef[(size_t)(e0 + row) * 128 + c16 * 4]);
        }
        CP_COMMIT();
    }

    if (t < 128) { sBg[t] = bgp[t]; sBf[t] = bfp[t]; }

    // One-time: load + transpose W matrices into resident SMEM as fp16
    for (int m = 0; m < 2; m++) {
        const float* W = m ? Wf : Wg;
        char* buf = sW + m * WBUF;
        for (int idx = t; idx < 16384; idx += 512) {
            int k = idx >> 7, n = idx & 127;
            *reinterpret_cast<__half*>(buf + n * AB + k * 2) = __float2half_rn(W[idx]);
        }
    }
    CP_WAIT0();
    __syncthreads();

    // Convert tile0 into A buffer 0
    #pragma unroll
    for (int i = 0; i < 8; i++) {
        int idx = t + i * 512;
        int row = idx >> 5, c16 = idx & 31;
        float4 v = *reinterpret_cast<const float4*>(sS + row * SPITCH + c16 * 16);
        *reinterpret_cast<uint2*>(sA + row * AB + c16 * 8) = make_uint2(
            pack_h2(__float2half_rn(v.x), __float2half_rn(v.y)),
            pack_h2(__float2half_rn(v.z), __float2half_rn(v.w)));
    }
    __syncthreads();   // A[0] published; stage consumed

    // Prefetch tile0+grid into stage (in flight across first iteration's mma)
    {
        int tn = tile0 + gridDim.x;
        if (tn >= ntiles) tn = tile0;
        const int en = tn * 128;
        #pragma unroll
        for (int i = 0; i < 8; i++) {
            int idx = t + i * 512;
            int row = idx >> 5, c16 = idx & 31;
            cp16(sbS + (uint32_t)(row * SPITCH + c16 * 16),
                 &ef[(size_t)(en + row) * 128 + c16 * 4]);
        }
        CP_COMMIT();
    }

    // ldmatrix lane addressing (canonical patterns)
    const int ra = lane & 15;
    const int ka = (lane >> 4) * 16;
    const int rb = (lane & 7) + ((lane >> 4) & 1) * 8;
    const int kb = ((lane >> 3) & 1) * 16;

    const uint32_t aoff0 = sbA + (uint32_t)((wm * 32 + ra) * AB + ka);
    const uint32_t boff  = sbW + (uint32_t)((wn * 32 + rb) * AB + kb);

    int cur = 0;
    for (int tile = tile0; tile < ntiles; tile += gridDim.x) {
        const int e0 = tile * 128;

        // Per-thread edge indices for the 2 rows this thread reduces (LDG,
        // latency hidden under mma below). Row: wm*32+mt*16+(lane>>2)+pl*8.
        int srcR[2], dstR[2];
        #pragma unroll
        for (int mt = 0; mt < 2; mt++) {
            int r = wm * 32 + mt * 16 + (lane >> 2) + pl * 8;
            int2 p = *reinterpret_cast<const int2*>(&eidx[(size_t)(e0 + r) * 2]);
            srcR[mt] = p.x; dstR[mt] = p.y;
        }
        if (t < 128)
            atomicAdd(&g_counts[eidx[(size_t)(e0 + t) * 2]], 1.0f);

        // mma on A[cur] — fp16 accumulators: acc[m][mt][nt][2] u32
        const uint32_t aoff = aoff0 + (uint32_t)(cur * WBUF);
        uint32_t acc[2][2][4][2];
        #pragma unroll
        for (int m = 0; m < 2; m++)
            #pragma unroll
            for (int mt = 0; mt < 2; mt++)
                #pragma unroll
                for (int nt = 0; nt < 4; nt++) {
                    acc[m][mt][nt][0] = 0u; acc[m][mt][nt][1] = 0u;
                }

        #pragma unroll
        for (int ks = 0; ks < 8; ks++) {
            uint32_t ah[2][4];
            ldsm_x4(ah[0], aoff + ks * 32);
            ldsm_x4(ah[1], aoff + 16 * AB + ks * 32);
            #pragma unroll
            for (int m = 0; m < 2; m++) {
                uint32_t buf = boff + (uint32_t)(m * WBUF);
                uint32_t bh[8];
                ldsm_x4(&bh[0], buf + ks * 32);
                ldsm_x4(&bh[4], buf + (uint32_t)(16 * AB) + ks * 32);
                #pragma unroll
                for (int mt = 0; mt < 2; mt++)
                    #pragma unroll
                    for (int nt = 0; nt < 4; nt++)
                        mma_fp16acc(acc[m][mt][nt], ah[mt], &bh[nt * 2]);
            }
        }

        CP_WAIT0();        // stage (tile+grid) landed
        __syncthreads();   // all mma reads of A[cur] done; stage visible

        // Convert stage -> A[nxt]
        {
            char* An = sA + (cur ^ 1) * WBUF;
            #pragma unroll
            for (int i = 0; i < 8; i++) {
                int idx = t + i * 512;
                int row = idx >> 5, c16 = idx & 31;
                float4 v = *reinterpret_cast<const float4*>(sS + row * SPITCH + c16 * 16);
                *reinterpret_cast<uint2*>(An + row * AB + c16 * 8) = make_uint2(
                    pack_h2(__float2half_rn(v.x), __float2half_rn(v.y)),
                    pack_h2(__float2half_rn(v.z), __float2half_rn(v.w)));
            }
        }
        __syncthreads();   // A[nxt] published; stage consumed by everyone

        // Issue prefetch for tile+2*grid (lands during epilogue+next mma)
        {
            int tn = tile + 2 * gridDim.x;
            if (tn >= ntiles) tn = tile;
            const int en = tn * 128;
            #pragma unroll
            for (int i = 0; i < 8; i++) {
                int idx = t + i * 512;
                int row = idx >> 5, c16 = idx & 31;
                cp16(sbS + (uint32_t)(row * SPITCH + c16 * 16),
                     &ef[(size_t)(en + row) * 128 + c16 * 4]);
            }
            CP_COMMIT();
        }

        // Epilogue (no trailing barrier — overlaps next iteration's mma).
        // fp16-frag pair-exchange: even lane sends reg1 (row r+8), odd sends
        // reg0 (row r); each side assembles 4 consecutive cols of its row.
        #pragma unroll
        for (int mt = 0; mt < 2; mt++) {
            const float* hp = &g_hidden[(size_t)dstR[mt] * 128];
            float* op = &out[(size_t)srcR[mt] * 128];
            #pragma unroll
            for (int nt = 0; nt < 4; nt++) {
                const int C = wn * 32 + nt * 8 + cb;
                float2 gv[2], fv[2];   // [0] = cols C,C+1 ; [1] = cols C+2,C+3
                #pragma unroll
                for (int m = 0; m < 2; m++) {
                    uint32_t own0 = acc[m][mt][nt][0];
                    uint32_t own1 = acc[m][mt][nt][1];
                    uint32_t send = pl ? own0 : own1;
                    uint32_t recv = __shfl_xor_sync(0xffffffffu, send, 1);
                    uint32_t lo = pl ? recv : own0;   // cols C,C+1 of own row
                    uint32_t hi = pl ? own1 : recv;   // cols C+2,C+3 of own row
                    float2 flo = __half22float2(*reinterpret_cast<__half2*>(&lo));
                    float2 fhi = __half22float2(*reinterpret_cast<__half2*>(&hi));
                    if (m == 0) { gv[0] = flo; gv[1] = fhi; }
                    else        { fv[0] = flo; fv[1] = fhi; }
                }

                float4 nb  = *reinterpret_cast<const float4*>(hp + C);
                float4 bg4 = *reinterpret_cast<const float4*>(sBg + C);
                float4 bf4 = *reinterpret_cast<const float4*>(sBf + C);
                float g0 = sigmoid_fast(gv[0].x + bg4.x);
                float g1 = sigmoid_fast(gv[0].y + bg4.y);
                float g2 = sigmoid_fast(gv[1].x + bg4.z);
                float g3 = sigmoid_fast(gv[1].y + bg4.w);
                float m0 = g0 * (fv[0].x + bf4.x) * nb.x;
                float m1 = g1 * (fv[0].y + bf4.y) * nb.y;
                float m2 = g2 * (fv[1].x + bf4.z) * nb.z;
                float m3 = g3 * (fv[1].y + bf4.w) * nb.w;
                red_add_v4(op + C, m0, m1, m2, m3);
            }
        }

        cur ^= 1;
    }
}

// ---------------------------------------------------------------------------
// K3: finalize — out = relu(bn(hidden + sums/max(counts,1)))
// ---------------------------------------------------------------------------
__global__ void finalize_kernel(const float* __restrict__ gamma,
                                const float* __restrict__ beta,
                                const float* __restrict__ mean,
                                const float* __restrict__ var,
                                float* __restrict__ out) {
    int idx = blockIdx.x * blockDim.x + threadIdx.x;
    const int total = N_NODES * 32;
    if (idx >= total) return;
    int node = idx >> 5;
    int q    = idx & 31;
    float inv = 1.f / fmaxf(g_counts[node], 1.f);

    float4 s  = reinterpret_cast<float4*>(out)[idx];
    float4 h  = *reinterpret_cast<const float4*>(&g_hidden[node * D + q * 4]);
    float4 mu = *reinterpret_cast<const float4*>(&mean[q * 4]);
    float4 vr = *reinterpret_cast<const float4*>(&var[q * 4]);
    float4 ga = *reinterpret_cast<const float4*>(&gamma[q * 4]);
    float4 be = *reinterpret_cast<const float4*>(&beta[q * 4]);

    float4 o;
    o.x = fmaxf((h.x + s.x * inv - mu.x) * rsqrtf(vr.x + BN_EPS) * ga.x + be.x, 0.f);
    o.y = fmaxf((h.y + s.y * inv - mu.y) * rsqrtf(vr.y + BN_EPS) * ga.y + be.y, 0.f);
    o.z = fmaxf((h.z + s.z * inv - mu.z) * rsqrtf(vr.z + BN_EPS) * ga.z + be.z, 0.f);
    o.w = fmaxf((h.w + s.w * inv - mu.w) * rsqrtf(vr.w + BN_EPS) * ga.w + be.w, 0.f);
    reinterpret_cast<float4*>(out)[idx] = o;
}

// ---------------------------------------------------------------------------
// launch
// ---------------------------------------------------------------------------
extern "C" void kernel_launch(void* const* d_in, const int* in_sizes, int n_in,
                              void* d_out, int out_size) {
    const float* nf    = (const float*)d_in[0];
    const float* ef    = (const float*)d_in[1];
    const float* Wn    = (const float*)d_in[2];
    const float* bn_   = (const float*)d_in[3];
    const float* Wg    = (const float*)d_in[4];
    const float* bg    = (const float*)d_in[5];
    const float* Wf    = (const float*)d_in[6];
    const float* bf    = (const float*)d_in[7];
    const float* gamma = (const float*)d_in[8];
    const float* beta  = (const float*)d_in[9];
    const float* mean  = (const float*)d_in[10];
    const float* var   = (const float*)d_in[11];
    const int*   eidx  = (const int*)d_in[12];
    float* out = (float*)d_out;

    const int node_smem = (128 * PAD + NT * PAD) * (int)sizeof(float);

    int dev = 0, nsm = 148;
    cudaGetDevice(&dev);
    cudaDeviceGetAttribute(&nsm, cudaDevAttrMultiProcessorCount, dev);
    cudaFuncSetAttribute(node_gemm_kernel, cudaFuncAttributeMaxDynamicSharedMemorySize, node_smem);
    cudaFuncSetAttribute(edge_kernel,      cudaFuncAttributeMaxDynamicSharedMemorySize, EK_SMEM);

    zero_kernel<<<512, 256>>>(out);
    node_gemm_kernel<<<2 * nsm, 256, node_smem>>>(nf, Wn, bn_);
    edge_kernel<<<nsm, 512, EK_SMEM>>>(ef, Wg, bg, Wf, bf, eidx, out);
    finalize_kernel<<<(N_NODES * 32 + 255) / 256, 256>>>(gamma, beta, mean, var, out);
}

// round 13
// speedup vs baseline: 3.8184x; 1.0816x over previous
#include <cuda_runtime.h>
#include <cuda_fp16.h>
#include <cstdint>

#define N_NODES 50000
#define N_EDGES 800000
#define D 128
#define BN_EPS 1e-3f

#define AB 272         // bytes per fp16 smem row (136 fp16, pitch)
#define WBUF 34816     // bytes per 128x136 fp16 buffer
#define SPITCH 544     // stage fp32 row pitch bytes (512 data + 32 pad)

// Scratch
__device__ float g_hidden[N_NODES * D];
__device__ float g_counts[N_NODES];

// ---------------------------------------------------------------------------
// helpers
// ---------------------------------------------------------------------------
__device__ __forceinline__ uint32_t smem_u32(const void* p) {
    uint32_t a;
    asm("{ .reg .u64 t; cvta.to.shared.u64 t, %1; cvt.u32.u64 %0, t; }" : "=r"(a) : "l"(p));
    return a;
}

__device__ __forceinline__ void red_add_v4(float* addr, float a, float b, float c, float d) {
    asm volatile("red.global.add.v4.f32 [%0], {%1, %2, %3, %4};"
                 :: "l"(addr), "f"(a), "f"(b), "f"(c), "f"(d) : "memory");
}

__device__ __forceinline__ void ldsm_x4(uint32_t* r, uint32_t addr) {
    asm volatile("ldmatrix.sync.aligned.m8n8.x4.shared.b16 {%0,%1,%2,%3}, [%4];"
                 : "=r"(r[0]), "=r"(r[1]), "=r"(r[2]), "=r"(r[3]) : "r"(addr));
}

// fp32-accumulator fp16 mma (rate identical to f16-acc per R12 measurement)
__device__ __forceinline__ void mma_f32acc(float* c, const uint32_t* a, const uint32_t* b) {
    asm volatile("mma.sync.aligned.m16n8k16.row.col.f32.f16.f16.f32 "
                 "{%0,%1,%2,%3}, {%4,%5,%6,%7}, {%8,%9}, {%0,%1,%2,%3};"
                 : "+f"(c[0]), "+f"(c[1]), "+f"(c[2]), "+f"(c[3])
                 : "r"(a[0]), "r"(a[1]), "r"(a[2]), "r"(a[3]), "r"(b[0]), "r"(b[1]));
}

// fp16-accumulator mma (edge kernel; R12-passing)
__device__ __forceinline__ void mma_fp16acc(uint32_t* c, const uint32_t* a, const uint32_t* b) {
    asm volatile("mma.sync.aligned.m16n8k16.row.col.f16.f16.f16.f16 "
                 "{%0,%1}, {%2,%3,%4,%5}, {%6,%7}, {%0,%1};"
                 : "+r"(c[0]), "+r"(c[1])
                 : "r"(a[0]), "r"(a[1]), "r"(a[2]), "r"(a[3]), "r"(b[0]), "r"(b[1]));
}

__device__ __forceinline__ uint32_t pack_h2(__half lo, __half hi) {
    return (uint32_t)__half_as_ushort(lo) | ((uint32_t)__half_as_ushort(hi) << 16);
}

__device__ __forceinline__ float tanh_fast(float x) {
    float y; asm("tanh.approx.f32 %0, %1;" : "=f"(y) : "f"(x)); return y;
}
__device__ __forceinline__ float sigmoid_fast(float x) {
    return fmaf(tanh_fast(0.5f * x), 0.5f, 0.5f);
}

__device__ __forceinline__ void cp16(uint32_t saddr, const void* g) {
    asm volatile("cp.async.cg.shared.global [%0], [%1], 16;" :: "r"(saddr), "l"(g));
}
#define CP_COMMIT() asm volatile("cp.async.commit_group;" ::: "memory")
#define CP_WAIT0()  asm volatile("cp.async.wait_group 0;" ::: "memory")

// ---------------------------------------------------------------------------
// K1: node_hidden = nf @ W_node + b_node  via fp16 mma (fp32 acc) + fused
//     zeroing of out/counts (replaces zero_kernel).
// 512 threads, warp grid 4(M) x 4(N), warp tile 32x32; tile M=128 nodes.
// SMEM: [0] bias[128] f32 (512B) | [1024] A fp16 [128][136] | [35840] W^T fp16
// total 70656. 391 tiles (last partial: 50000 = 390*128 + 80).
// ---------------------------------------------------------------------------
#define NG_SMEM 70656

__global__ __launch_bounds__(512, 1)
void node_gemm_kernel(const float* __restrict__ nf,
                      const float* __restrict__ W,
                      const float* __restrict__ b,
                      float* __restrict__ out) {
    extern __shared__ __align__(16) char smem[];
    float* sB = reinterpret_cast<float*>(smem);
    char*  sA = smem + 1024;
    char*  sW = smem + 35840;

    const int t = threadIdx.x, w = t >> 5, lane = t & 31;
    const int wm = w & 3, wn = w >> 2;

    // Fused zeroing of out + counts (no ordering needed vs GEMM within kernel)
    {
        int gid = blockIdx.x * 512 + t;
        int gstride = gridDim.x * 512;
        const int nv4 = N_NODES * D / 4;
        float4 z = make_float4(0.f, 0.f, 0.f, 0.f);
        for (int i = gid; i < nv4; i += gstride)
            reinterpret_cast<float4*>(out)[i] = z;
        for (int i = gid; i < N_NODES; i += gstride)
            g_counts[i] = 0.f;
    }

    if (t < 128) sB[t] = b[t];

    // Load + transpose W_node into SMEM fp16 (W^T: row n holds W[.][n])
    for (int idx = t; idx < 16384; idx += 512) {
        int k = idx >> 7, n = idx & 127;
        *reinterpret_cast<__half*>(sW + n * AB + k * 2) = __float2half_rn(W[idx]);
    }
    __syncthreads();

    const uint32_t sbA = smem_u32(sA);
    const uint32_t sbW = smem_u32(sW);

    const int ra = lane & 15;
    const int ka = (lane >> 4) * 16;
    const int rb = (lane & 7) + ((lane >> 4) & 1) * 8;
    const int kb = ((lane >> 3) & 1) * 16;
    const uint32_t aoff = sbA + (uint32_t)((wm * 32 + ra) * AB + ka);
    const uint32_t boff = sbW + (uint32_t)((wn * 32 + rb) * AB + kb);

    const int ntiles = (N_NODES + 127) / 128;  // 391
    for (int tile = blockIdx.x; tile < ntiles; tile += gridDim.x) {
        __syncthreads();   // protect sA reuse
        const int r0 = tile * 128;
        // Load A tile fp32 -> fp16 (guard rows >= N_NODES with zeros)
        #pragma unroll
        for (int i = 0; i < 8; i++) {
            int idx = t + i * 512;
            int row = idx >> 5, c16 = idx & 31;
            int grow = r0 + row;
            float4 v = make_float4(0.f, 0.f, 0.f, 0.f);
            if (grow < N_NODES)
                v = *reinterpret_cast<const float4*>(&nf[(size_t)grow * 128 + c16 * 4]);
            *reinterpret_cast<uint2*>(sA + row * AB + c16 * 8) = make_uint2(
                pack_h2(__float2half_rn(v.x), __float2half_rn(v.y)),
                pack_h2(__float2half_rn(v.z), __float2half_rn(v.w)));
        }
        __syncthreads();

        float acc[2][4][4];
        #pragma unroll
        for (int mt = 0; mt < 2; mt++)
            #pragma unroll
            for (int nt = 0; nt < 4; nt++)
                #pragma unroll
                for (int i = 0; i < 4; i++) acc[mt][nt][i] = 0.f;

        #pragma unroll
        for (int ks = 0; ks < 8; ks++) {
            uint32_t ah[2][4];
            ldsm_x4(ah[0], aoff + ks * 32);
            ldsm_x4(ah[1], aoff + 16 * AB + ks * 32);
            uint32_t bh[8];
            ldsm_x4(&bh[0], boff + ks * 32);
            ldsm_x4(&bh[4], boff + (uint32_t)(16 * AB) + ks * 32);
            #pragma unroll
            for (int mt = 0; mt < 2; mt++)
                #pragma unroll
                for (int nt = 0; nt < 4; nt++)
                    mma_f32acc(acc[mt][nt], ah[mt], &bh[nt * 2]);
        }

        // Store hidden + bias (fragment rows lane>>2 (+8), cols (lane&3)*2)
        #pragma unroll
        for (int mt = 0; mt < 2; mt++) {
            #pragma unroll
            for (int rr = 0; rr < 2; rr++) {
                int grow = r0 + wm * 32 + mt * 16 + (lane >> 2) + rr * 8;
                if (grow < N_NODES) {
                    float* hp = &g_hidden[(size_t)grow * 128];
                    #pragma unroll
                    for (int nt = 0; nt < 4; nt++) {
                        int c = wn * 32 + nt * 8 + (lane & 3) * 2;
                        float2 o;
                        o.x = acc[mt][nt][rr * 2 + 0] + sB[c];
                        o.y = acc[mt][nt][rr * 2 + 1] + sB[c + 1];
                        *reinterpret_cast<float2*>(hp + c) = o;
                    }
                }
            }
        }
    }
}

// ---------------------------------------------------------------------------
// K2: edge kernel — byte-identical logic to R12 (passed @431.6us)
// ---------------------------------------------------------------------------
#define EK_SMEM 210944
#define OFF_A   2048
#define OFF_W   71680
#define OFF_S   141312

__global__ __launch_bounds__(512, 1)
void edge_kernel(const float* __restrict__ ef,
                 const float* __restrict__ Wg, const float* __restrict__ bgp,
                 const float* __restrict__ Wf, const float* __restrict__ bfp,
                 const int*   __restrict__ eidx,
                 float* __restrict__ out) {
    extern __shared__ __align__(16) char smem[];
    float* sBg  = reinterpret_cast<float*>(smem + 1024);
    float* sBf  = reinterpret_cast<float*>(smem + 1536);
    char*  sA   = smem + OFF_A;
    char*  sW   = smem + OFF_W;
    char*  sS   = smem + OFF_S;

    const int t = threadIdx.x, w = t >> 5, lane = t & 31;
    const int wm = w & 3, wn = w >> 2;
    const int pl = lane & 1;
    const int cb = (lane & 2) * 2;

    const uint32_t sbA = smem_u32(sA);
    const uint32_t sbW = smem_u32(sW);
    const uint32_t sbS = smem_u32(sS);

    const int ntiles = N_EDGES / 128;
    const int tile0 = blockIdx.x;

    {
        const int e0 = tile0 * 128;
        #pragma unroll
        for (int i = 0; i < 8; i++) {
            int idx = t + i * 512;
            int row = idx >> 5, c16 = idx & 31;
            cp16(sbS + (uint32_t)(row * SPITCH + c16 * 16),
                 &ef[(size_t)(e0 + row) * 128 + c16 * 4]);
        }
        CP_COMMIT();
    }

    if (t < 128) { sBg[t] = bgp[t]; sBf[t] = bfp[t]; }

    for (int m = 0; m < 2; m++) {
        const float* W = m ? Wf : Wg;
        char* buf = sW + m * WBUF;
        for (int idx = t; idx < 16384; idx += 512) {
            int k = idx >> 7, n = idx & 127;
            *reinterpret_cast<__half*>(buf + n * AB + k * 2) = __float2half_rn(W[idx]);
        }
    }
    CP_WAIT0();
    __syncthreads();

    #pragma unroll
    for (int i = 0; i < 8; i++) {
        int idx = t + i * 512;
        int row = idx >> 5, c16 = idx & 31;
        float4 v = *reinterpret_cast<const float4*>(sS + row * SPITCH + c16 * 16);
        *reinterpret_cast<uint2*>(sA + row * AB + c16 * 8) = make_uint2(
            pack_h2(__float2half_rn(v.x), __float2half_rn(v.y)),
            pack_h2(__float2half_rn(v.z), __float2half_rn(v.w)));
    }
    __syncthreads();

    {
        int tn = tile0 + gridDim.x;
        if (tn >= ntiles) tn = tile0;
        const int en = tn * 128;
        #pragma unroll
        for (int i = 0; i < 8; i++) {
            int idx = t + i * 512;
            int row = idx >> 5, c16 = idx & 31;
            cp16(sbS + (uint32_t)(row * SPITCH + c16 * 16),
                 &ef[(size_t)(en + row) * 128 + c16 * 4]);
        }
        CP_COMMIT();
    }

    const int ra = lane & 15;
    const int ka = (lane >> 4) * 16;
    const int rb = (lane & 7) + ((lane >> 4) & 1) * 8;
    const int kb = ((lane >> 3) & 1) * 16;

    const uint32_t aoff0 = sbA + (uint32_t)((wm * 32 + ra) * AB + ka);
    const uint32_t boff  = sbW + (uint32_t)((wn * 32 + rb) * AB + kb);

    int cur = 0;
    for (int tile = tile0; tile < ntiles; tile += gridDim.x) {
        const int e0 = tile * 128;

        int srcR[2], dstR[2];
        #pragma unroll
        for (int mt = 0; mt < 2; mt++) {
            int r = wm * 32 + mt * 16 + (lane >> 2) + pl * 8;
            int2 p = *reinterpret_cast<const int2*>(&eidx[(size_t)(e0 + r) * 2]);
            srcR[mt] = p.x; dstR[mt] = p.y;
        }
        if (t < 128)
            atomicAdd(&g_counts[eidx[(size_t)(e0 + t) * 2]], 1.0f);

        const uint32_t aoff = aoff0 + (uint32_t)(cur * WBUF);
        uint32_t acc[2][2][4][2];
        #pragma unroll
        for (int m = 0; m < 2; m++)
            #pragma unroll
            for (int mt = 0; mt < 2; mt++)
                #pragma unroll
                for (int nt = 0; nt < 4; nt++) {
                    acc[m][mt][nt][0] = 0u; acc[m][mt][nt][1] = 0u;
                }

        #pragma unroll
        for (int ks = 0; ks < 8; ks++) {
            uint32_t ah[2][4];
            ldsm_x4(ah[0], aoff + ks * 32);
            ldsm_x4(ah[1], aoff + 16 * AB + ks * 32);
            #pragma unroll
            for (int m = 0; m < 2; m++) {
                uint32_t buf = boff + (uint32_t)(m * WBUF);
                uint32_t bh[8];
                ldsm_x4(&bh[0], buf + ks * 32);
                ldsm_x4(&bh[4], buf + (uint32_t)(16 * AB) + ks * 32);
                #pragma unroll
                for (int mt = 0; mt < 2; mt++)
                    #pragma unroll
                    for (int nt = 0; nt < 4; nt++)
                        mma_fp16acc(acc[m][mt][nt], ah[mt], &bh[nt * 2]);
            }
        }

        CP_WAIT0();
        __syncthreads();

        {
            char* An = sA + (cur ^ 1) * WBUF;
            #pragma unroll
            for (int i = 0; i < 8; i++) {
                int idx = t + i * 512;
                int row = idx >> 5, c16 = idx & 31;
                float4 v = *reinterpret_cast<const float4*>(sS + row * SPITCH + c16 * 16);
                *reinterpret_cast<uint2*>(An + row * AB + c16 * 8) = make_uint2(
                    pack_h2(__float2half_rn(v.x), __float2half_rn(v.y)),
                    pack_h2(__float2half_rn(v.z), __float2half_rn(v.w)));
            }
        }
        __syncthreads();

        {
            int tn = tile + 2 * gridDim.x;
            if (tn >= ntiles) tn = tile;
            const int en = tn * 128;
            #pragma unroll
            for (int i = 0; i < 8; i++) {
                int idx = t + i * 512;
                int row = idx >> 5, c16 = idx & 31;
                cp16(sbS + (uint32_t)(row * SPITCH + c16 * 16),
                     &ef[(size_t)(en + row) * 128 + c16 * 4]);
            }
            CP_COMMIT();
        }

        #pragma unroll
        for (int mt = 0; mt < 2; mt++) {
            const float* hp = &g_hidden[(size_t)dstR[mt] * 128];
            float* op = &out[(size_t)srcR[mt] * 128];
            #pragma unroll
            for (int nt = 0; nt < 4; nt++) {
                const int C = wn * 32 + nt * 8 + cb;
                float2 gv[2], fv[2];
                #pragma unroll
                for (int m = 0; m < 2; m++) {
                    uint32_t own0 = acc[m][mt][nt][0];
                    uint32_t own1 = acc[m][mt][nt][1];
                    uint32_t send = pl ? own0 : own1;
                    uint32_t recv = __shfl_xor_sync(0xffffffffu, send, 1);
                    uint32_t lo = pl ? recv : own0;
                    uint32_t hi = pl ? own1 : recv;
                    float2 flo = __half22float2(*reinterpret_cast<__half2*>(&lo));
                    float2 fhi = __half22float2(*reinterpret_cast<__half2*>(&hi));
                    if (m == 0) { gv[0] = flo; gv[1] = fhi; }
                    else        { fv[0] = flo; fv[1] = fhi; }
                }

                float4 nb  = *reinterpret_cast<const float4*>(hp + C);
                float4 bg4 = *reinterpret_cast<const float4*>(sBg + C);
                float4 bf4 = *reinterpret_cast<const float4*>(sBf + C);
                float g0 = sigmoid_fast(gv[0].x + bg4.x);
                float g1 = sigmoid_fast(gv[0].y + bg4.y);
                float g2 = sigmoid_fast(gv[1].x + bg4.z);
                float g3 = sigmoid_fast(gv[1].y + bg4.w);
                float m0 = g0 * (fv[0].x + bf4.x) * nb.x;
                float m1 = g1 * (fv[0].y + bf4.y) * nb.y;
                float m2 = g2 * (fv[1].x + bf4.z) * nb.z;
                float m3 = g3 * (fv[1].y + bf4.w) * nb.w;
                red_add_v4(op + C, m0, m1, m2, m3);
            }
        }

        cur ^= 1;
    }
}

// ---------------------------------------------------------------------------
// K3: finalize — out = relu(bn(hidden + sums/max(counts,1)))
// ---------------------------------------------------------------------------
__global__ void finalize_kernel(const float* __restrict__ gamma,
                                const float* __restrict__ beta,
                                const float* __restrict__ mean,
                                const float* __restrict__ var,
                                float* __restrict__ out) {
    int idx = blockIdx.x * blockDim.x + threadIdx.x;
    const int total = N_NODES * 32;
    if (idx >= total) return;
    int node = idx >> 5;
    int q    = idx & 31;
    float inv = 1.f / fmaxf(g_counts[node], 1.f);

    float4 s  = reinterpret_cast<float4*>(out)[idx];
    float4 h  = *reinterpret_cast<const float4*>(&g_hidden[node * D + q * 4]);
    float4 mu = *reinterpret_cast<const float4*>(&mean[q * 4]);
    float4 vr = *reinterpret_cast<const float4*>(&var[q * 4]);
    float4 ga = *reinterpret_cast<const float4*>(&gamma[q * 4]);
    float4 be = *reinterpret_cast<const float4*>(&beta[q * 4]);

    float4 o;
    o.x = fmaxf((h.x + s.x * inv - mu.x) * rsqrtf(vr.x + BN_EPS) * ga.x + be.x, 0.f);
    o.y = fmaxf((h.y + s.y * inv - mu.y) * rsqrtf(vr.y + BN_EPS) * ga.y + be.y, 0.f);
    o.z = fmaxf((h.z + s.z * inv - mu.z) * rsqrtf(vr.z + BN_EPS) * ga.z + be.z, 0.f);
    o.w = fmaxf((h.w + s.w * inv - mu.w) * rsqrtf(vr.w + BN_EPS) * ga.w + be.w, 0.f);
    reinterpret_cast<float4*>(out)[idx] = o;
}

// ---------------------------------------------------------------------------
// launch
// ---------------------------------------------------------------------------
extern "C" void kernel_launch(void* const* d_in, const int* in_sizes, int n_in,
                              void* d_out, int out_size) {
    const float* nf    = (const float*)d_in[0];
    const float* ef    = (const float*)d_in[1];
    const float* Wn    = (const float*)d_in[2];
    const float* bn_   = (const float*)d_in[3];
    const float* Wg    = (const float*)d_in[4];
    const float* bg    = (const float*)d_in[5];
    const float* Wf    = (const float*)d_in[6];
    const float* bf    = (const float*)d_in[7];
    const float* gamma = (const float*)d_in[8];
    const float* beta  = (const float*)d_in[9];
    const float* mean  = (const float*)d_in[10];
    const float* var   = (const float*)d_in[11];
    const int*   eidx  = (const int*)d_in[12];
    float* out = (float*)d_out;

    int dev = 0, nsm = 148;
    cudaGetDevice(&dev);
    cudaDeviceGetAttribute(&nsm, cudaDevAttrMultiProcessorCount, dev);
    cudaFuncSetAttribute(node_gemm_kernel, cudaFuncAttributeMaxDynamicSharedMemorySize, NG_SMEM);
    cudaFuncSetAttribute(edge_kernel,      cudaFuncAttributeMaxDynamicSharedMemorySize, EK_SMEM);

    node_gemm_kernel<<<nsm, 512, NG_SMEM>>>(nf, Wn, bn_, out);
    edge_kernel<<<nsm, 512, EK_SMEM>>>(ef, Wg, bg, Wf, bf, eidx, out);
    finalize_kernel<<<(N_NODES * 32 + 255) / 256, 256>>>(gamma, beta, mean, var, out);
}